// round 1
// baseline (speedup 1.0000x reference)
#include <cuda_runtime.h>
#include <math.h>

#define BL    8000
#define DM    512
#define DFF   2048
#define NL    4
#define LSEQ  1000
#define NB    8
#define NH    8
#define DKH   64
#define PP    16

// ---------------- scratch (device globals; no allocation allowed) ----------------
__device__ float g_h  [BL * DM];
__device__ float g_q  [BL * DM];
__device__ float g_k  [BL * DM];
__device__ float g_v  [BL * DM];
__device__ float g_ctx[BL * DM];
__device__ float g_t1 [BL * DM];
__device__ float g_t2 [BL * DM];
__device__ float g_ff [BL * DFF];
__device__ float g_qp [BL * NH * PP];
__device__ float g_kp [BL * NH * PP];

// ---------------- embed: h = x @ emb_w + emb_b + pe[l] ----------------
__global__ __launch_bounds__(128)
void embed_kernel(const float* __restrict__ x, const float* __restrict__ ew,
                  const float* __restrict__ eb, const float* __restrict__ pe,
                  float* __restrict__ h)
{
    __shared__ float sx[7];
    int row = blockIdx.x;          // 0..7999
    int l   = row % LSEQ;
    int tid = threadIdx.x;
    if (tid < 7) sx[tid] = x[row * 7 + tid];
    __syncthreads();
    for (int d = tid; d < DM; d += 128) {
        float a = eb[d] + pe[l * DM + d];
#pragma unroll
        for (int f = 0; f < 7; f++) a += sx[f] * ew[f * DM + d];
        h[(long)row * DM + d] = a;
    }
}

// ---------------- generic SGEMM: C = act(A[M,K] @ W[K,N] + bias[N]) ----------------
// BM=BN=128, BK=8, 256 threads, 8x8 per-thread tile. N % 128 == 0, K % 8 == 0, M guarded.
__global__ __launch_bounds__(256)
void gemm_kernel(const float* __restrict__ A, const float* __restrict__ W,
                 const float* __restrict__ bias, float* __restrict__ C,
                 int M, int N, int K, int relu)
{
    __shared__ float sA[8][128];
    __shared__ float sB[8][128];
    int tid  = threadIdx.x;
    int bn   = blockIdx.x * 128;
    int bm   = blockIdx.y * 128;
    int arow = tid >> 1;
    int acol = (tid & 1) << 2;
    int brow = tid >> 5;
    int bcol = (tid & 31) << 2;
    int ty   = tid >> 4, tx = tid & 15;

    float acc[8][8];
#pragma unroll
    for (int i = 0; i < 8; i++)
#pragma unroll
        for (int j = 0; j < 8; j++) acc[i][j] = 0.f;

    const bool  avalid = (bm + arow) < M;
    const float* Aptr  = A + (long)(bm + arow) * K + acol;
    const float* Wptr  = W + (long)brow * N + bn + bcol;

    for (int k0 = 0; k0 < K; k0 += 8) {
        float4 av = make_float4(0.f, 0.f, 0.f, 0.f);
        if (avalid) av = *(const float4*)(Aptr + k0);
        sA[acol + 0][arow] = av.x;
        sA[acol + 1][arow] = av.y;
        sA[acol + 2][arow] = av.z;
        sA[acol + 3][arow] = av.w;
        *(float4*)&sB[brow][bcol] = *(const float4*)(Wptr + (long)k0 * N);
        __syncthreads();
#pragma unroll
        for (int kk = 0; kk < 8; kk++) {
            float ra[8], rb[8];
            *(float4*)&ra[0] = *(float4*)&sA[kk][ty * 8];
            *(float4*)&ra[4] = *(float4*)&sA[kk][ty * 8 + 4];
            *(float4*)&rb[0] = *(float4*)&sB[kk][tx * 8];
            *(float4*)&rb[4] = *(float4*)&sB[kk][tx * 8 + 4];
#pragma unroll
            for (int i = 0; i < 8; i++)
#pragma unroll
                for (int j = 0; j < 8; j++) acc[i][j] += ra[i] * rb[j];
        }
        __syncthreads();
    }
#pragma unroll
    for (int i = 0; i < 8; i++) {
        int row = bm + ty * 8 + i;
        if (row < M) {
#pragma unroll
            for (int j = 0; j < 8; j++) {
                int col = bn + tx * 8 + j;
                float val = acc[i][j] + bias[col];
                if (relu) val = fmaxf(val, 0.f);
                C[(long)row * N + col] = val;
            }
        }
    }
}

// ---------------- learned-mask projection: [64000,64] @ [64,16] + b ----------------
__global__ __launch_bounds__(128)
void lmproj_kernel(const float* __restrict__ q, const float* __restrict__ w,
                   const float* __restrict__ b, float* __restrict__ o)
{
    __shared__ float sw[64 * 16];
    __shared__ float sq[8 * 64];
    int tid = threadIdx.x;
    int r0  = blockIdx.x * 8;
    for (int i = tid; i < 1024; i += 128) sw[i] = w[i];
    for (int i = tid; i < 512;  i += 128) sq[i] = q[(long)r0 * 64 + i];
    __syncthreads();
    int rr = tid >> 4, p = tid & 15;
    float a = b[p];
#pragma unroll
    for (int d = 0; d < 64; d++) a += sq[rr * 64 + d] * sw[d * 16 + p];
    o[(long)(r0 + rr) * 16 + p] = a;
}

// ---------------- fused attention ----------------
__device__ __forceinline__ float fast_tanh(float x)
{
    x = fminf(fmaxf(x, -15.f), 15.f);
    float e = __expf(2.f * x);
    return (e - 1.f) / (e + 1.f);
}

#define ATT_SMEM (19008 * 4)

__global__ __launch_bounds__(256)
void attn_kernel(const float* __restrict__ q, const float* __restrict__ kkg,
                 const float* __restrict__ vvg, const float* __restrict__ qp,
                 const float* __restrict__ kp, float* __restrict__ ctx)
{
    extern __shared__ float smem[];
    float* sQ   = smem;           // 64*65
    float* sK   = sQ + 4160;
    float* sV   = sK + 4160;
    float* sS   = sV + 4160;
    float* sQP  = sS + 4160;      // 64*17
    float* sKP  = sQP + 1088;
    float* sM   = sKP + 1088;     // 64
    float* sSum = sM + 64;        // 64
    float* sF   = sSum + 64;      // 64

    int tid = threadIdx.x;
    int bid = blockIdx.x;
    int qt = bid & 15;
    int h  = (bid >> 4) & 7;
    int b  = bid >> 7;
    int l0 = qt << 6;

    for (int i = tid; i < 64 * 64; i += 256) {
        int r = i >> 6, d = i & 63;
        int l = l0 + r;
        sQ[r * 65 + d] = (l < LSEQ) ? q[(((b * LSEQ + l) * NH + h) << 6) + d] : 0.f;
    }
    for (int i = tid; i < 64 * 16; i += 256) {
        int r = i >> 4, p = i & 15;
        int l = l0 + r;
        sQP[r * 17 + p] = (l < LSEQ) ? qp[(((b * LSEQ + l) * NH + h) << 4) + p] : 0.f;
    }
    if (tid < 64) { sM[tid] = -1e30f; sSum[tid] = 0.f; }

    int ty = tid >> 4, tx = tid & 15;
    float acc[4][4];
#pragma unroll
    for (int i = 0; i < 4; i++)
#pragma unroll
        for (int j = 0; j < 4; j++) acc[i][j] = 0.f;

    __syncthreads();

    for (int st = 0; st < 16; st++) {
        int s0 = st << 6;
        for (int i = tid; i < 64 * 64; i += 256) {
            int r = i >> 6, d = i & 63;
            int s = s0 + r;
            if (s < LSEQ) {
                int gi = (((b * LSEQ + s) * NH + h) << 6) + d;
                sK[r * 65 + d] = kkg[gi];
                sV[r * 65 + d] = vvg[gi];
            } else { sK[r * 65 + d] = 0.f; sV[r * 65 + d] = 0.f; }
        }
        for (int i = tid; i < 64 * 16; i += 256) {
            int r = i >> 4, p = i & 15;
            int s = s0 + r;
            sKP[r * 17 + p] = (s < LSEQ) ? kp[(((b * LSEQ + s) * NH + h) << 4) + p] : 0.f;
        }
        __syncthreads();

        // scores: 64q x 64s over 64 (qk) + 16 (learned mask) dims
        float sc[4][4], scp[4][4];
#pragma unroll
        for (int i = 0; i < 4; i++)
#pragma unroll
            for (int j = 0; j < 4; j++) { sc[i][j] = 0.f; scp[i][j] = 0.f; }

        for (int d = 0; d < 64; d++) {
            float aq[4], bk[4];
#pragma unroll
            for (int i = 0; i < 4; i++) aq[i] = sQ[(ty * 4 + i) * 65 + d];
#pragma unroll
            for (int j = 0; j < 4; j++) bk[j] = sK[(tx * 4 + j) * 65 + d];
#pragma unroll
            for (int i = 0; i < 4; i++)
#pragma unroll
                for (int j = 0; j < 4; j++) sc[i][j] += aq[i] * bk[j];
        }
#pragma unroll
        for (int p = 0; p < 16; p++) {
            float aq[4], bk[4];
#pragma unroll
            for (int i = 0; i < 4; i++) aq[i] = sQP[(ty * 4 + i) * 17 + p];
#pragma unroll
            for (int j = 0; j < 4; j++) bk[j] = sKP[(tx * 4 + j) * 17 + p];
#pragma unroll
            for (int i = 0; i < 4; i++)
#pragma unroll
                for (int j = 0; j < 4; j++) scp[i][j] += aq[i] * bk[j];
        }
#pragma unroll
        for (int i = 0; i < 4; i++)
#pragma unroll
            for (int j = 0; j < 4; j++)
                sS[(ty * 4 + i) * 65 + tx * 4 + j] = sc[i][j] * 0.125f + fast_tanh(scp[i][j]);
        __syncthreads();

        // online softmax: 4 threads per query row
        int qr = tid >> 2, part = tid & 3;
        float mold = sM[qr];
        float mx = mold;
#pragma unroll
        for (int t = 0; t < 16; t++) {
            int s = (part << 4) + t;
            float val = (s0 + s < LSEQ) ? sS[qr * 65 + s] : -1e30f;
            mx = fmaxf(mx, val);
        }
        mx = fmaxf(mx, __shfl_xor_sync(0xffffffffu, mx, 1));
        mx = fmaxf(mx, __shfl_xor_sync(0xffffffffu, mx, 2));
        float psum = 0.f;
#pragma unroll
        for (int t = 0; t < 16; t++) {
            int s = (part << 4) + t;
            float val = (s0 + s < LSEQ) ? sS[qr * 65 + s] : -1e30f;
            float pv = __expf(val - mx);
            sS[qr * 65 + s] = pv;
            psum += pv;
        }
        psum += __shfl_xor_sync(0xffffffffu, psum, 1);
        psum += __shfl_xor_sync(0xffffffffu, psum, 2);
        if (part == 0) {
            float factor = __expf(mold - mx);
            sSum[qr] = sSum[qr] * factor + psum;
            sM[qr]   = mx;
            sF[qr]   = factor;
        }
        __syncthreads();

        // rescale accumulators + accumulate P @ V
        float fr[4];
#pragma unroll
        for (int i = 0; i < 4; i++) fr[i] = sF[ty * 4 + i];
#pragma unroll
        for (int i = 0; i < 4; i++)
#pragma unroll
            for (int j = 0; j < 4; j++) acc[i][j] *= fr[i];

        for (int s = 0; s < 64; s++) {
            float pq[4], vr[4];
#pragma unroll
            for (int i = 0; i < 4; i++) pq[i] = sS[(ty * 4 + i) * 65 + s];
#pragma unroll
            for (int j = 0; j < 4; j++) vr[j] = sV[s * 65 + tx * 4 + j];
#pragma unroll
            for (int i = 0; i < 4; i++)
#pragma unroll
                for (int j = 0; j < 4; j++) acc[i][j] += pq[i] * vr[j];
        }
        __syncthreads();
    }

    float rs[4];
#pragma unroll
    for (int i = 0; i < 4; i++) rs[i] = 1.f / sSum[ty * 4 + i];
#pragma unroll
    for (int i = 0; i < 4; i++) {
        int l = l0 + ty * 4 + i;
        if (l < LSEQ) {
#pragma unroll
            for (int j = 0; j < 4; j++)
                ctx[(((b * LSEQ + l) * NH + h) << 6) + tx * 4 + j] = acc[i][j] * rs[i];
        }
    }
}

// ---------------- LayerNorm: out = LN(a (+ y)) * g + b ----------------
__global__ __launch_bounds__(128)
void ln_kernel(float* __restrict__ out, const float* __restrict__ a,
               const float* __restrict__ y, const float* __restrict__ g,
               const float* __restrict__ bb)
{
    int row = blockIdx.x, tid = threadIdx.x;
    float4 v = ((const float4*)(a + (long)row * DM))[tid];
    if (y) {
        float4 vy = ((const float4*)(y + (long)row * DM))[tid];
        v.x += vy.x; v.y += vy.y; v.z += vy.z; v.w += vy.w;
    }
    float s  = v.x + v.y + v.z + v.w;
    float sq = v.x * v.x + v.y * v.y + v.z * v.z + v.w * v.w;
#pragma unroll
    for (int o = 16; o > 0; o >>= 1) {
        s  += __shfl_xor_sync(0xffffffffu, s,  o);
        sq += __shfl_xor_sync(0xffffffffu, sq, o);
    }
    __shared__ float shs[4], shq[4];
    int wid = tid >> 5;
    if ((tid & 31) == 0) { shs[wid] = s; shq[wid] = sq; }
    __syncthreads();
    s  = shs[0] + shs[1] + shs[2] + shs[3];
    sq = shq[0] + shq[1] + shq[2] + shq[3];
    float mean = s * (1.f / DM);
    float var  = sq * (1.f / DM) - mean * mean;
    float rstd = rsqrtf(var + 1e-5f);
    float4 gg = ((const float4*)g)[tid];
    float4 bv = ((const float4*)bb)[tid];
    float4 o4;
    o4.x = (v.x - mean) * rstd * gg.x + bv.x;
    o4.y = (v.y - mean) * rstd * gg.y + bv.y;
    o4.z = (v.z - mean) * rstd * gg.z + bv.z;
    o4.w = (v.w - mean) * rstd * gg.w + bv.w;
    ((float4*)(out + (long)row * DM))[tid] = o4;
}

// ---------------- final FC on last token ----------------
__global__ __launch_bounds__(64)
void fc_kernel(const float* __restrict__ hin, const float* __restrict__ w,
               const float* __restrict__ b, float* __restrict__ out)
{
    __shared__ float sh[512];
    int tid = threadIdx.x;
    int bb  = blockIdx.x;
    const float* row = hin + ((long)bb * LSEQ + (LSEQ - 1)) * DM;
    for (int i = tid; i < 512; i += 64) sh[i] = row[i];
    __syncthreads();
    if (tid < 50) {
        float a = b[tid];
#pragma unroll 8
        for (int d = 0; d < 512; d++) a += sh[d] * w[d * 50 + tid];
        out[bb * 50 + tid] = a;
    }
}

// ---------------- launch ----------------
extern "C" void kernel_launch(void* const* d_in, const int* in_sizes, int n_in,
                              void* d_out, int out_size)
{
    const float* x     = (const float*)d_in[0];
    const float* emb_w = (const float*)d_in[1];
    const float* emb_b = (const float*)d_in[2];
    const float* pe    = (const float*)d_in[3];
    const float* Wq    = (const float*)d_in[4];
    const float* bq    = (const float*)d_in[5];
    const float* Wk    = (const float*)d_in[6];
    const float* bk    = (const float*)d_in[7];
    const float* Wv    = (const float*)d_in[8];
    const float* bv    = (const float*)d_in[9];
    const float* Wo    = (const float*)d_in[10];
    const float* bo    = (const float*)d_in[11];
    const float* W1    = (const float*)d_in[12];
    const float* b1    = (const float*)d_in[13];
    const float* W2    = (const float*)d_in[14];
    const float* b2    = (const float*)d_in[15];
    const float* g1    = (const float*)d_in[16];
    const float* be1   = (const float*)d_in[17];
    const float* g2    = (const float*)d_in[18];
    const float* be2   = (const float*)d_in[19];
    const float* lm_qw = (const float*)d_in[20];
    const float* lm_qb = (const float*)d_in[21];
    const float* lm_kw = (const float*)d_in[22];
    const float* lm_kb = (const float*)d_in[23];
    const float* gn    = (const float*)d_in[24];
    const float* bn    = (const float*)d_in[25];
    const float* fc_w  = (const float*)d_in[26];
    const float* fc_b  = (const float*)d_in[27];
    float* out = (float*)d_out;

    float *h, *q, *k, *v, *ctx, *t1, *t2, *ff, *qpb, *kpb;
    cudaGetSymbolAddress((void**)&h,   g_h);
    cudaGetSymbolAddress((void**)&q,   g_q);
    cudaGetSymbolAddress((void**)&k,   g_k);
    cudaGetSymbolAddress((void**)&v,   g_v);
    cudaGetSymbolAddress((void**)&ctx, g_ctx);
    cudaGetSymbolAddress((void**)&t1,  g_t1);
    cudaGetSymbolAddress((void**)&t2,  g_t2);
    cudaGetSymbolAddress((void**)&ff,  g_ff);
    cudaGetSymbolAddress((void**)&qpb, g_qp);
    cudaGetSymbolAddress((void**)&kpb, g_kp);

    cudaFuncSetAttribute(attn_kernel, cudaFuncAttributeMaxDynamicSharedMemorySize, ATT_SMEM);

    embed_kernel<<<BL, 128>>>(x, emb_w, emb_b, pe, h);

    dim3 g512(4, 63);    // N=512,  M=8000
    dim3 g2048(16, 63);  // N=2048, M=8000

    for (int i = 0; i < NL; i++) {
        const float* Wq_i = Wq + (long)i * DM * DM;
        const float* Wk_i = Wk + (long)i * DM * DM;
        const float* Wv_i = Wv + (long)i * DM * DM;
        const float* Wo_i = Wo + (long)i * DM * DM;
        const float* W1_i = W1 + (long)i * DM * DFF;
        const float* W2_i = W2 + (long)i * DFF * DM;

        gemm_kernel<<<g512, 256>>>(h, Wq_i, bq + i * DM, q, BL, DM, DM, 0);
        gemm_kernel<<<g512, 256>>>(h, Wk_i, bk + i * DM, k, BL, DM, DM, 0);
        gemm_kernel<<<g512, 256>>>(h, Wv_i, bv + i * DM, v, BL, DM, DM, 0);

        lmproj_kernel<<<BL, 128>>>(q, lm_qw, lm_qb, qpb);
        lmproj_kernel<<<BL, 128>>>(k, lm_kw, lm_kb, kpb);

        attn_kernel<<<NB * NH * 16, 256, ATT_SMEM>>>(q, k, v, qpb, kpb, ctx);

        gemm_kernel<<<g512, 256>>>(ctx, Wo_i, bo + i * DM, t1, BL, DM, DM, 0);
        ln_kernel<<<BL, 128>>>(h, h, t1, g1 + i * DM, be1 + i * DM);

        gemm_kernel<<<g2048, 256>>>(h, W1_i, b1 + i * DFF, ff, BL, DFF, DM, 1);
        gemm_kernel<<<g512, 256>>>(ff, W2_i, b2 + i * DM, t2, BL, DM, DFF, 0);

        ln_kernel<<<BL, 128>>>(t1, h, t2, g2 + i * DM, be2 + i * DM);
        ln_kernel<<<BL, 128>>>(h, t1, t2, g2 + i * DM, be2 + i * DM);
    }

    ln_kernel<<<BL, 128>>>(t1, h, (const float*)nullptr, gn, bn);
    fc_kernel<<<NB, 64>>>(t1, fc_w, fc_b, out);
}

// round 3
// speedup vs baseline: 1.0651x; 1.0651x over previous
#include <cuda_runtime.h>
#include <cuda_bf16.h>
#include <math.h>
#include <stdint.h>

#define BL    8000
#define MPAD  8064
#define DM    512
#define DFF   2048
#define NL    4
#define LSEQ  1000
#define NB    8
#define NH    8
#define DKH   64
#define PP    16

// ---------------- scratch (device globals; no allocation allowed) ----------------
__device__ float g_h  [BL * DM];
__device__ float g_q  [BL * DM];
__device__ float g_k  [BL * DM];
__device__ float g_v  [BL * DM];
__device__ float g_ctx[BL * DM];
__device__ float g_t1 [BL * DM];
__device__ float g_t2 [BL * DM];
__device__ float g_ff [BL * DFF];
__device__ float g_qp [BL * NH * PP];
__device__ float g_kp [BL * NH * PP];

// bf16 split weight buffers (transposed to [N,K])
__device__ __nv_bfloat16 g_wqh[NL * DM * DM];
__device__ __nv_bfloat16 g_wql[NL * DM * DM];
__device__ __nv_bfloat16 g_wkh[NL * DM * DM];
__device__ __nv_bfloat16 g_wkl[NL * DM * DM];
__device__ __nv_bfloat16 g_wvh[NL * DM * DM];
__device__ __nv_bfloat16 g_wvl[NL * DM * DM];
__device__ __nv_bfloat16 g_woh[NL * DM * DM];
__device__ __nv_bfloat16 g_wol[NL * DM * DM];
__device__ __nv_bfloat16 g_w1h[NL * DM * DFF];
__device__ __nv_bfloat16 g_w1l[NL * DM * DFF];
__device__ __nv_bfloat16 g_w2h[NL * DFF * DM];
__device__ __nv_bfloat16 g_w2l[NL * DFF * DM];
// bf16 split activation buffers (padded to MPAD rows, max K = DFF)
__device__ __nv_bfloat16 g_ah[MPAD * DFF];
__device__ __nv_bfloat16 g_al[MPAD * DFF];

// ================= PTX helpers (baseline ISA only — no tcgen05 on compute_103) ======
__device__ __forceinline__ uint32_t smem_u32(const void* p) {
    uint32_t a;
    asm("{ .reg .u64 t; cvta.to.shared.u64 t, %1; cvt.u32.u64 %0, t; }" : "=r"(a) : "l"(p));
    return a;
}
__device__ __forceinline__ void cpa16(uint32_t s, const void* g) {
    asm volatile("cp.async.cg.shared.global [%0], [%1], 16;" :: "r"(s), "l"(g));
}
#define CP_COMMIT() asm volatile("cp.async.commit_group;" ::: "memory")
#define CP_WAIT(n)  asm volatile("cp.async.wait_group %0;" :: "n"(n) : "memory")

__device__ __forceinline__ void ldsm4(uint32_t* r, uint32_t addr) {
    asm volatile("ldmatrix.sync.aligned.m8n8.x4.shared.b16 {%0,%1,%2,%3}, [%4];"
                 : "=r"(r[0]), "=r"(r[1]), "=r"(r[2]), "=r"(r[3]) : "r"(addr));
}
__device__ __forceinline__ void mma16816(float* d, const uint32_t* a, const uint32_t* b) {
    asm volatile("mma.sync.aligned.m16n8k16.row.col.f32.bf16.bf16.f32 "
                 "{%0,%1,%2,%3}, {%4,%5,%6,%7}, {%8,%9}, {%0,%1,%2,%3};"
                 : "+f"(d[0]), "+f"(d[1]), "+f"(d[2]), "+f"(d[3])
                 : "r"(a[0]), "r"(a[1]), "r"(a[2]), "r"(a[3]), "r"(b[0]), "r"(b[1]));
}

// ---------------- weight transpose + bf16 split: in[K,N] -> out[N,K] hi/lo ----------------
__global__ __launch_bounds__(256)
void wsplit_kernel(const float* __restrict__ in, __nv_bfloat16* __restrict__ oh,
                   __nv_bfloat16* __restrict__ ol, int K, int N)
{
    __shared__ float s[32][33];
    int n0 = blockIdx.x * 32, k0 = blockIdx.y * 32;
    int tx = threadIdx.x & 31, ty = threadIdx.x >> 5;
#pragma unroll
    for (int r = 0; r < 32; r += 8)
        s[r + ty][tx] = in[(size_t)(k0 + r + ty) * N + n0 + tx];
    __syncthreads();
#pragma unroll
    for (int r = 0; r < 32; r += 8) {
        float v = s[tx][r + ty];
        __nv_bfloat16 hi = __float2bfloat16(v);
        __nv_bfloat16 lo = __float2bfloat16(v - __bfloat162float(hi));
        size_t o = (size_t)(n0 + r + ty) * K + k0 + tx;
        oh[o] = hi; ol[o] = lo;
    }
}

// ---------------- activation bf16 split (row-pad to MPAD with zeros) ----------------
__global__ __launch_bounds__(256)
void asplit_kernel(const float* __restrict__ in, __nv_bfloat16* __restrict__ oh,
                   __nv_bfloat16* __restrict__ ol, int K)
{
    int i4 = blockIdx.x * 256 + threadIdx.x;
    int K4 = K >> 2;
    int row = i4 / K4;
    float4 v = make_float4(0.f, 0.f, 0.f, 0.f);
    if (row < BL) v = ((const float4*)in)[i4];
    __nv_bfloat16 h0 = __float2bfloat16(v.x), h1 = __float2bfloat16(v.y);
    __nv_bfloat16 h2 = __float2bfloat16(v.z), h3 = __float2bfloat16(v.w);
    __nv_bfloat162 hh0; hh0.x = h0; hh0.y = h1;
    __nv_bfloat162 hh1; hh1.x = h2; hh1.y = h3;
    __nv_bfloat162 ll0, ll1;
    ll0.x = __float2bfloat16(v.x - __bfloat162float(h0));
    ll0.y = __float2bfloat16(v.y - __bfloat162float(h1));
    ll1.x = __float2bfloat16(v.z - __bfloat162float(h2));
    ll1.y = __float2bfloat16(v.w - __bfloat162float(h3));
    ((__nv_bfloat162*)oh)[i4 * 2]     = hh0;
    ((__nv_bfloat162*)oh)[i4 * 2 + 1] = hh1;
    ((__nv_bfloat162*)ol)[i4 * 2]     = ll0;
    ((__nv_bfloat162*)ol)[i4 * 2 + 1] = ll1;
}

// ---------------- HMMA bf16-split GEMM: C[M,N] = A[M,K] @ B[N,K]^T + bias ----------------
// CTA 128x128, BK=32, 8 warps (warp tile 32x64), cp.async double buffer.
// smem per buffer: 4 tiles (Ah,Al,Bh,Bl) of 128 rows x 40 bf16 (stride-40 pad) = 40960B.
#define GS_TILE   10240          // bytes per 128x40 bf16 tile
#define GS_BUF    40960          // 4 tiles
#define MMA_SMEM  (2 * GS_BUF)   // 81920

__global__ __launch_bounds__(256, 2)
void mma_gemm(const __nv_bfloat16* __restrict__ Ah, const __nv_bfloat16* __restrict__ Al,
              const __nv_bfloat16* __restrict__ Bh, const __nv_bfloat16* __restrict__ Bl,
              const float* __restrict__ bias, float* __restrict__ C,
              int N, int K, int relu)
{
    extern __shared__ char smraw[];
    uint32_t sb = smem_u32(smraw);

    int tid = threadIdx.x;
    int l = tid & 31, w = tid >> 5;
    int wm = w >> 1, wn = w & 1;
    int bn = blockIdx.x << 7, bm = blockIdx.y << 7;
    size_t rowb = (size_t)K * 2;

    const char* gAh = (const char*)Ah + (size_t)bm * rowb;
    const char* gAl = (const char*)Al + (size_t)bm * rowb;
    const char* gBh = (const char*)Bh + (size_t)bn * rowb;
    const char* gBl = (const char*)Bl + (size_t)bn * rowb;

    float d[2][8][4];
#pragma unroll
    for (int i = 0; i < 2; i++)
#pragma unroll
        for (int j = 0; j < 8; j++)
#pragma unroll
            for (int t = 0; t < 4; t++) d[i][j][t] = 0.f;

    // ldmatrix per-lane base offsets (bytes) within a tile
    uint32_t aoff = (uint32_t)((wm * 32 + (l & 7) + ((l >> 3) & 1) * 8) * 80 + ((l >> 4) & 1) * 16);
    uint32_t boff = (uint32_t)((wn * 64 + (l & 7) + ((l >> 4) & 1) * 8) * 80 + ((l >> 3) & 1) * 16);

    const int S = K >> 5;

    // ---- stage loader ----
    // 512 16B-chunks per tile; each thread does 2 per tile.
    int lrow0 = tid >> 2,        lch0 = tid & 3;
    int lrow1 = (tid + 256) >> 2, lch1 = (tid + 256) & 3;

#define LOAD_STAGE(stg, buf) do { \
    size_t go0 = (size_t)lrow0 * rowb + (size_t)(stg) * 64 + lch0 * 16; \
    size_t go1 = (size_t)lrow1 * rowb + (size_t)(stg) * 64 + lch1 * 16; \
    uint32_t so0 = sb + (buf) * GS_BUF + lrow0 * 80 + lch0 * 16; \
    uint32_t so1 = sb + (buf) * GS_BUF + lrow1 * 80 + lch1 * 16; \
    cpa16(so0,               gAh + go0); \
    cpa16(so0 + GS_TILE,     gAl + go0); \
    cpa16(so0 + 2 * GS_TILE, gBh + go0); \
    cpa16(so0 + 3 * GS_TILE, gBl + go0); \
    cpa16(so1,               gAh + go1); \
    cpa16(so1 + GS_TILE,     gAl + go1); \
    cpa16(so1 + 2 * GS_TILE, gBh + go1); \
    cpa16(so1 + 3 * GS_TILE, gBl + go1); \
} while (0)

    LOAD_STAGE(0, 0);
    CP_COMMIT();

    for (int s = 0; s < S; s++) {
        int p = s & 1;
        if (s + 1 < S) {
            LOAD_STAGE(s + 1, p ^ 1);
            CP_COMMIT();
            CP_WAIT(1);
        } else {
            CP_WAIT(0);
        }
        __syncthreads();

        uint32_t bufo = sb + p * GS_BUF;
#pragma unroll
        for (int kk = 0; kk < 2; kk++) {
            uint32_t kb = kk * 32;
            uint32_t ahf[2][4], bhf[4][4];
            ldsm4(ahf[0], bufo + aoff + kb);
            ldsm4(ahf[1], bufo + aoff + 1280 + kb);
#pragma unroll
            for (int n2 = 0; n2 < 4; n2++)
                ldsm4(bhf[n2], bufo + 2 * GS_TILE + boff + n2 * 1280 + kb);
#pragma unroll
            for (int mt = 0; mt < 2; mt++)
#pragma unroll
                for (int nt = 0; nt < 8; nt++)
                    mma16816(d[mt][nt], ahf[mt], &bhf[nt >> 1][(nt & 1) * 2]);

            uint32_t blf[4][4];
#pragma unroll
            for (int n2 = 0; n2 < 4; n2++)
                ldsm4(blf[n2], bufo + 3 * GS_TILE + boff + n2 * 1280 + kb);
#pragma unroll
            for (int mt = 0; mt < 2; mt++)
#pragma unroll
                for (int nt = 0; nt < 8; nt++)
                    mma16816(d[mt][nt], ahf[mt], &blf[nt >> 1][(nt & 1) * 2]);

            uint32_t alf[2][4];
            ldsm4(alf[0], bufo + GS_TILE + aoff + kb);
            ldsm4(alf[1], bufo + GS_TILE + aoff + 1280 + kb);
#pragma unroll
            for (int mt = 0; mt < 2; mt++)
#pragma unroll
                for (int nt = 0; nt < 8; nt++)
                    mma16816(d[mt][nt], alf[mt], &bhf[nt >> 1][(nt & 1) * 2]);
        }
        __syncthreads();
    }

    // ---- epilogue: bias (+relu), direct stores ----
#pragma unroll
    for (int mt = 0; mt < 2; mt++) {
        int r0 = bm + wm * 32 + mt * 16 + (l >> 2);
        int r1 = r0 + 8;
#pragma unroll
        for (int nt = 0; nt < 8; nt++) {
            int c = bn + wn * 64 + nt * 8 + (l & 3) * 2;
            float b0 = bias[c], b1 = bias[c + 1];
            float v0 = d[mt][nt][0] + b0, v1 = d[mt][nt][1] + b1;
            float v2 = d[mt][nt][2] + b0, v3 = d[mt][nt][3] + b1;
            if (relu) {
                v0 = fmaxf(v0, 0.f); v1 = fmaxf(v1, 0.f);
                v2 = fmaxf(v2, 0.f); v3 = fmaxf(v3, 0.f);
            }
            if (r0 < BL) { float2 t = {v0, v1}; *(float2*)&C[(size_t)r0 * N + c] = t; }
            if (r1 < BL) { float2 t = {v2, v3}; *(float2*)&C[(size_t)r1 * N + c] = t; }
        }
    }
}

// ---------------- embed: h = x @ emb_w + emb_b + pe[l] ----------------
__global__ __launch_bounds__(128)
void embed_kernel(const float* __restrict__ x, const float* __restrict__ ew,
                  const float* __restrict__ eb, const float* __restrict__ pe,
                  float* __restrict__ h)
{
    __shared__ float sx[7];
    int row = blockIdx.x;
    int l   = row % LSEQ;
    int tid = threadIdx.x;
    if (tid < 7) sx[tid] = x[row * 7 + tid];
    __syncthreads();
    for (int d = tid; d < DM; d += 128) {
        float a = eb[d] + pe[l * DM + d];
#pragma unroll
        for (int f = 0; f < 7; f++) a += sx[f] * ew[f * DM + d];
        h[(long)row * DM + d] = a;
    }
}

// ---------------- learned-mask projection ----------------
__global__ __launch_bounds__(128)
void lmproj_kernel(const float* __restrict__ q, const float* __restrict__ w,
                   const float* __restrict__ b, float* __restrict__ o)
{
    __shared__ float sw[64 * 16];
    __shared__ float sq[8 * 64];
    int tid = threadIdx.x;
    int r0  = blockIdx.x * 8;
    for (int i = tid; i < 1024; i += 128) sw[i] = w[i];
    for (int i = tid; i < 512;  i += 128) sq[i] = q[(long)r0 * 64 + i];
    __syncthreads();
    int rr = tid >> 4, p = tid & 15;
    float a = b[p];
#pragma unroll
    for (int d = 0; d < 64; d++) a += sq[rr * 64 + d] * sw[d * 16 + p];
    o[(long)(r0 + rr) * 16 + p] = a;
}

// ---------------- fused attention (fp32) ----------------
__device__ __forceinline__ float fast_tanh(float x)
{
    x = fminf(fmaxf(x, -15.f), 15.f);
    float e = __expf(2.f * x);
    return (e - 1.f) / (e + 1.f);
}

#define ATT_SMEM (19008 * 4)

__global__ __launch_bounds__(256)
void attn_kernel(const float* __restrict__ q, const float* __restrict__ kkg,
                 const float* __restrict__ vvg, const float* __restrict__ qp,
                 const float* __restrict__ kp, float* __restrict__ ctx)
{
    extern __shared__ float smem[];
    float* sQ   = smem;
    float* sK   = sQ + 4160;
    float* sV   = sK + 4160;
    float* sS   = sV + 4160;
    float* sQP  = sS + 4160;
    float* sKP  = sQP + 1088;
    float* sM   = sKP + 1088;
    float* sSum = sM + 64;
    float* sF   = sSum + 64;

    int tid = threadIdx.x;
    int bid = blockIdx.x;
    int qt = bid & 15;
    int h  = (bid >> 4) & 7;
    int b  = bid >> 7;
    int l0 = qt << 6;

    for (int i = tid; i < 64 * 64; i += 256) {
        int r = i >> 6, d = i & 63;
        int l = l0 + r;
        sQ[r * 65 + d] = (l < LSEQ) ? q[(((b * LSEQ + l) * NH + h) << 6) + d] : 0.f;
    }
    for (int i = tid; i < 64 * 16; i += 256) {
        int r = i >> 4, p = i & 15;
        int l = l0 + r;
        sQP[r * 17 + p] = (l < LSEQ) ? qp[(((b * LSEQ + l) * NH + h) << 4) + p] : 0.f;
    }
    if (tid < 64) { sM[tid] = -1e30f; sSum[tid] = 0.f; }

    int ty = tid >> 4, tx = tid & 15;
    float acc[4][4];
#pragma unroll
    for (int i = 0; i < 4; i++)
#pragma unroll
        for (int j = 0; j < 4; j++) acc[i][j] = 0.f;

    __syncthreads();

    for (int st = 0; st < 16; st++) {
        int s0 = st << 6;
        for (int i = tid; i < 64 * 64; i += 256) {
            int r = i >> 6, d = i & 63;
            int s = s0 + r;
            if (s < LSEQ) {
                int gi = (((b * LSEQ + s) * NH + h) << 6) + d;
                sK[r * 65 + d] = kkg[gi];
                sV[r * 65 + d] = vvg[gi];
            } else { sK[r * 65 + d] = 0.f; sV[r * 65 + d] = 0.f; }
        }
        for (int i = tid; i < 64 * 16; i += 256) {
            int r = i >> 4, p = i & 15;
            int s = s0 + r;
            sKP[r * 17 + p] = (s < LSEQ) ? kp[(((b * LSEQ + s) * NH + h) << 4) + p] : 0.f;
        }
        __syncthreads();

        float sc[4][4], scp[4][4];
#pragma unroll
        for (int i = 0; i < 4; i++)
#pragma unroll
            for (int j = 0; j < 4; j++) { sc[i][j] = 0.f; scp[i][j] = 0.f; }

        for (int d = 0; d < 64; d++) {
            float aq[4], bk[4];
#pragma unroll
            for (int i = 0; i < 4; i++) aq[i] = sQ[(ty * 4 + i) * 65 + d];
#pragma unroll
            for (int j = 0; j < 4; j++) bk[j] = sK[(tx * 4 + j) * 65 + d];
#pragma unroll
            for (int i = 0; i < 4; i++)
#pragma unroll
                for (int j = 0; j < 4; j++) sc[i][j] += aq[i] * bk[j];
        }
#pragma unroll
        for (int p = 0; p < 16; p++) {
            float aq[4], bk[4];
#pragma unroll
            for (int i = 0; i < 4; i++) aq[i] = sQP[(ty * 4 + i) * 17 + p];
#pragma unroll
            for (int j = 0; j < 4; j++) bk[j] = sKP[(tx * 4 + j) * 17 + p];
#pragma unroll
            for (int i = 0; i < 4; i++)
#pragma unroll
                for (int j = 0; j < 4; j++) scp[i][j] += aq[i] * bk[j];
        }
#pragma unroll
        for (int i = 0; i < 4; i++)
#pragma unroll
            for (int j = 0; j < 4; j++)
                sS[(ty * 4 + i) * 65 + tx * 4 + j] = sc[i][j] * 0.125f + fast_tanh(scp[i][j]);
        __syncthreads();

        int qr = tid >> 2, part = tid & 3;
        float mold = sM[qr];
        float mx = mold;
#pragma unroll
        for (int t = 0; t < 16; t++) {
            int s = (part << 4) + t;
            float val = (s0 + s < LSEQ) ? sS[qr * 65 + s] : -1e30f;
            mx = fmaxf(mx, val);
        }
        mx = fmaxf(mx, __shfl_xor_sync(0xffffffffu, mx, 1));
        mx = fmaxf(mx, __shfl_xor_sync(0xffffffffu, mx, 2));
        float psum = 0.f;
#pragma unroll
        for (int t = 0; t < 16; t++) {
            int s = (part << 4) + t;
            float val = (s0 + s < LSEQ) ? sS[qr * 65 + s] : -1e30f;
            float pv = __expf(val - mx);
            sS[qr * 65 + s] = pv;
            psum += pv;
        }
        psum += __shfl_xor_sync(0xffffffffu, psum, 1);
        psum += __shfl_xor_sync(0xffffffffu, psum, 2);
        if (part == 0) {
            float factor = __expf(mold - mx);
            sSum[qr] = sSum[qr] * factor + psum;
            sM[qr]   = mx;
            sF[qr]   = factor;
        }
        __syncthreads();

        float fr[4];
#pragma unroll
        for (int i = 0; i < 4; i++) fr[i] = sF[ty * 4 + i];
#pragma unroll
        for (int i = 0; i < 4; i++)
#pragma unroll
            for (int j = 0; j < 4; j++) acc[i][j] *= fr[i];

        for (int s = 0; s < 64; s++) {
            float pq[4], vr[4];
#pragma unroll
            for (int i = 0; i < 4; i++) pq[i] = sS[(ty * 4 + i) * 65 + s];
#pragma unroll
            for (int j = 0; j < 4; j++) vr[j] = sV[s * 65 + tx * 4 + j];
#pragma unroll
            for (int i = 0; i < 4; i++)
#pragma unroll
                for (int j = 0; j < 4; j++) acc[i][j] += pq[i] * vr[j];
        }
        __syncthreads();
    }

    float rs[4];
#pragma unroll
    for (int i = 0; i < 4; i++) rs[i] = 1.f / sSum[ty * 4 + i];
#pragma unroll
    for (int i = 0; i < 4; i++) {
        int l = l0 + ty * 4 + i;
        if (l < LSEQ) {
#pragma unroll
            for (int j = 0; j < 4; j++)
                ctx[(((b * LSEQ + l) * NH + h) << 6) + tx * 4 + j] = acc[i][j] * rs[i];
        }
    }
}

// ---------------- LayerNorm ----------------
__global__ __launch_bounds__(128)
void ln_kernel(float* __restrict__ out, const float* __restrict__ a,
               const float* __restrict__ y, const float* __restrict__ g,
               const float* __restrict__ bb)
{
    int row = blockIdx.x, tid = threadIdx.x;
    float4 v = ((const float4*)(a + (long)row * DM))[tid];
    if (y) {
        float4 vy = ((const float4*)(y + (long)row * DM))[tid];
        v.x += vy.x; v.y += vy.y; v.z += vy.z; v.w += vy.w;
    }
    float s  = v.x + v.y + v.z + v.w;
    float sq = v.x * v.x + v.y * v.y + v.z * v.z + v.w * v.w;
#pragma unroll
    for (int o = 16; o > 0; o >>= 1) {
        s  += __shfl_xor_sync(0xffffffffu, s,  o);
        sq += __shfl_xor_sync(0xffffffffu, sq, o);
    }
    __shared__ float shs[4], shq[4];
    int wid = tid >> 5;
    if ((tid & 31) == 0) { shs[wid] = s; shq[wid] = sq; }
    __syncthreads();
    s  = shs[0] + shs[1] + shs[2] + shs[3];
    sq = shq[0] + shq[1] + shq[2] + shq[3];
    float mean = s * (1.f / DM);
    float var  = sq * (1.f / DM) - mean * mean;
    float rstd = rsqrtf(var + 1e-5f);
    float4 gg = ((const float4*)g)[tid];
    float4 bv = ((const float4*)bb)[tid];
    float4 o4;
    o4.x = (v.x - mean) * rstd * gg.x + bv.x;
    o4.y = (v.y - mean) * rstd * gg.y + bv.y;
    o4.z = (v.z - mean) * rstd * gg.z + bv.z;
    o4.w = (v.w - mean) * rstd * gg.w + bv.w;
    ((float4*)(out + (long)row * DM))[tid] = o4;
}

// ---------------- final FC on last token ----------------
__global__ __launch_bounds__(64)
void fc_kernel(const float* __restrict__ hin, const float* __restrict__ w,
               const float* __restrict__ b, float* __restrict__ out)
{
    __shared__ float sh[512];
    int tid = threadIdx.x;
    int bb  = blockIdx.x;
    const float* row = hin + ((long)bb * LSEQ + (LSEQ - 1)) * DM;
    for (int i = tid; i < 512; i += 64) sh[i] = row[i];
    __syncthreads();
    if (tid < 50) {
        float a = b[tid];
#pragma unroll 8
        for (int d = 0; d < 512; d++) a += sh[d] * w[d * 50 + tid];
        out[bb * 50 + tid] = a;
    }
}

// ---------------- launch ----------------
extern "C" void kernel_launch(void* const* d_in, const int* in_sizes, int n_in,
                              void* d_out, int out_size)
{
    const float* x     = (const float*)d_in[0];
    const float* emb_w = (const float*)d_in[1];
    const float* emb_b = (const float*)d_in[2];
    const float* pe    = (const float*)d_in[3];
    const float* Wq    = (const float*)d_in[4];
    const float* bq    = (const float*)d_in[5];
    const float* Wk    = (const float*)d_in[6];
    const float* bk    = (const float*)d_in[7];
    const float* Wv    = (const float*)d_in[8];
    const float* bv    = (const float*)d_in[9];
    const float* Wo    = (const float*)d_in[10];
    const float* bo    = (const float*)d_in[11];
    const float* W1    = (const float*)d_in[12];
    const float* b1    = (const float*)d_in[13];
    const float* W2    = (const float*)d_in[14];
    const float* b2    = (const float*)d_in[15];
    const float* g1    = (const float*)d_in[16];
    const float* be1   = (const float*)d_in[17];
    const float* g2    = (const float*)d_in[18];
    const float* be2   = (const float*)d_in[19];
    const float* lm_qw = (const float*)d_in[20];
    const float* lm_qb = (const float*)d_in[21];
    const float* lm_kw = (const float*)d_in[22];
    const float* lm_kb = (const float*)d_in[23];
    const float* gn    = (const float*)d_in[24];
    const float* bn    = (const float*)d_in[25];
    const float* fc_w  = (const float*)d_in[26];
    const float* fc_b  = (const float*)d_in[27];
    float* out = (float*)d_out;

    float *h, *q, *k, *v, *ctx, *t1, *t2, *ff, *qpb, *kpb;
    cudaGetSymbolAddress((void**)&h,   g_h);
    cudaGetSymbolAddress((void**)&q,   g_q);
    cudaGetSymbolAddress((void**)&k,   g_k);
    cudaGetSymbolAddress((void**)&v,   g_v);
    cudaGetSymbolAddress((void**)&ctx, g_ctx);
    cudaGetSymbolAddress((void**)&t1,  g_t1);
    cudaGetSymbolAddress((void**)&t2,  g_t2);
    cudaGetSymbolAddress((void**)&ff,  g_ff);
    cudaGetSymbolAddress((void**)&qpb, g_qp);
    cudaGetSymbolAddress((void**)&kpb, g_kp);

    __nv_bfloat16 *wqh, *wql, *wkh, *wkl, *wvh, *wvl, *woh, *wol;
    __nv_bfloat16 *w1h, *w1l, *w2h, *w2l, *ah, *al;
    cudaGetSymbolAddress((void**)&wqh, g_wqh);
    cudaGetSymbolAddress((void**)&wql, g_wql);
    cudaGetSymbolAddress((void**)&wkh, g_wkh);
    cudaGetSymbolAddress((void**)&wkl, g_wkl);
    cudaGetSymbolAddress((void**)&wvh, g_wvh);
    cudaGetSymbolAddress((void**)&wvl, g_wvl);
    cudaGetSymbolAddress((void**)&woh, g_woh);
    cudaGetSymbolAddress((void**)&wol, g_wol);
    cudaGetSymbolAddress((void**)&w1h, g_w1h);
    cudaGetSymbolAddress((void**)&w1l, g_w1l);
    cudaGetSymbolAddress((void**)&w2h, g_w2h);
    cudaGetSymbolAddress((void**)&w2l, g_w2l);
    cudaGetSymbolAddress((void**)&ah,  g_ah);
    cudaGetSymbolAddress((void**)&al,  g_al);

    cudaFuncSetAttribute(attn_kernel, cudaFuncAttributeMaxDynamicSharedMemorySize, ATT_SMEM);
    cudaFuncSetAttribute(mma_gemm,    cudaFuncAttributeMaxDynamicSharedMemorySize, MMA_SMEM);

    // weight transpose + split (per replay; cheap)
    for (int i = 0; i < NL; i++) {
        long o512 = (long)i * DM * DM;
        long offf = (long)i * DM * DFF;
        wsplit_kernel<<<dim3(DM / 32, DM / 32), 256>>>(Wq + o512, wqh + o512, wql + o512, DM, DM);
        wsplit_kernel<<<dim3(DM / 32, DM / 32), 256>>>(Wk + o512, wkh + o512, wkl + o512, DM, DM);
        wsplit_kernel<<<dim3(DM / 32, DM / 32), 256>>>(Wv + o512, wvh + o512, wvl + o512, DM, DM);
        wsplit_kernel<<<dim3(DM / 32, DM / 32), 256>>>(Wo + o512, woh + o512, wol + o512, DM, DM);
        wsplit_kernel<<<dim3(DFF / 32, DM / 32), 256>>>(W1 + offf, w1h + offf, w1l + offf, DM, DFF);
        wsplit_kernel<<<dim3(DM / 32, DFF / 32), 256>>>(W2 + offf, w2h + offf, w2l + offf, DFF, DM);
    }

    embed_kernel<<<BL, 128>>>(x, emb_w, emb_b, pe, h);

    const int MT = MPAD / 128;     // 63
    dim3 gq(DM / 128, MT);         // (4, 63)
    dim3 gf1(DFF / 128, MT);       // (16, 63)
    const int split512  = MPAD * DM  / 1024;  // 4032 blocks
    const int split2048 = MPAD * DFF / 1024;  // 16128 blocks

    for (int i = 0; i < NL; i++) {
        long o512 = (long)i * DM * DM;
        long offf = (long)i * DM * DFF;

        asplit_kernel<<<split512, 256>>>(h, ah, al, DM);
        mma_gemm<<<gq, 256, MMA_SMEM>>>(ah, al, wqh + o512, wql + o512, bq + i * DM, q, DM, DM, 0);
        mma_gemm<<<gq, 256, MMA_SMEM>>>(ah, al, wkh + o512, wkl + o512, bk + i * DM, k, DM, DM, 0);
        mma_gemm<<<gq, 256, MMA_SMEM>>>(ah, al, wvh + o512, wvl + o512, bv + i * DM, v, DM, DM, 0);

        lmproj_kernel<<<BL, 128>>>(q, lm_qw, lm_qb, qpb);
        lmproj_kernel<<<BL, 128>>>(k, lm_kw, lm_kb, kpb);

        attn_kernel<<<NB * NH * 16, 256, ATT_SMEM>>>(q, k, v, qpb, kpb, ctx);

        asplit_kernel<<<split512, 256>>>(ctx, ah, al, DM);
        mma_gemm<<<gq, 256, MMA_SMEM>>>(ah, al, woh + o512, wol + o512, bo + i * DM, t1, DM, DM, 0);
        ln_kernel<<<BL, 128>>>(h, h, t1, g1 + i * DM, be1 + i * DM);

        asplit_kernel<<<split512, 256>>>(h, ah, al, DM);
        mma_gemm<<<gf1, 256, MMA_SMEM>>>(ah, al, w1h + offf, w1l + offf, b1 + i * DFF, ff, DFF, DM, 1);

        asplit_kernel<<<split2048, 256>>>(ff, ah, al, DFF);
        mma_gemm<<<gq, 256, MMA_SMEM>>>(ah, al, w2h + offf, w2l + offf, b2 + i * DM, t2, DM, DFF, 0);

        ln_kernel<<<BL, 128>>>(t1, h, t2, g2 + i * DM, be2 + i * DM);
        ln_kernel<<<BL, 128>>>(h, t1, t2, g2 + i * DM, be2 + i * DM);
    }

    ln_kernel<<<BL, 128>>>(t1, h, (const float*)nullptr, gn, bn);
    fc_kernel<<<NB, 64>>>(t1, fc_w, fc_b, out);
}

// round 7
// speedup vs baseline: 1.7072x; 1.6030x over previous
#include <cuda_runtime.h>
#include <cuda_bf16.h>
#include <math.h>
#include <stdint.h>

#define BL    8000
#define MPAD  8064
#define DM    512
#define DFF   2048
#define NL    4
#define LSEQ  1000
#define NB    8
#define NH    8
#define DKH   64
#define PP    16

// ---------------- scratch (device globals; no allocation allowed) ----------------
__device__ float g_h  [BL * DM];
__device__ float g_q  [BL * DM];
__device__ float g_k  [BL * DM];
__device__ float g_v  [BL * DM];
__device__ float g_t1 [BL * DM];
__device__ float g_t2 [BL * DM];
__device__ float g_qp [BL * NH * PP];
__device__ float g_kp [BL * NH * PP];

// bf16 split weight buffers (transposed to [N,K])
__device__ __nv_bfloat16 g_wqh[NL * DM * DM];
__device__ __nv_bfloat16 g_wql[NL * DM * DM];
__device__ __nv_bfloat16 g_wkh[NL * DM * DM];
__device__ __nv_bfloat16 g_wkl[NL * DM * DM];
__device__ __nv_bfloat16 g_wvh[NL * DM * DM];
__device__ __nv_bfloat16 g_wvl[NL * DM * DM];
__device__ __nv_bfloat16 g_woh[NL * DM * DM];
__device__ __nv_bfloat16 g_wol[NL * DM * DM];
__device__ __nv_bfloat16 g_w1h[NL * DM * DFF];
__device__ __nv_bfloat16 g_w1l[NL * DM * DFF];
__device__ __nv_bfloat16 g_w2h[NL * DFF * DM];
__device__ __nv_bfloat16 g_w2l[NL * DFF * DM];
// bf16 split activation buffers
__device__ __nv_bfloat16 g_ah [MPAD * DM];
__device__ __nv_bfloat16 g_al [MPAD * DM];
__device__ __nv_bfloat16 g_ffh[MPAD * DFF];
__device__ __nv_bfloat16 g_ffl[MPAD * DFF];

// ================= PTX helpers (baseline ISA only) =================
__device__ __forceinline__ uint32_t smem_u32(const void* p) {
    uint32_t a;
    asm("{ .reg .u64 t; cvta.to.shared.u64 t, %1; cvt.u32.u64 %0, t; }" : "=r"(a) : "l"(p));
    return a;
}
__device__ __forceinline__ void cpa16(uint32_t s, const void* g) {
    asm volatile("cp.async.cg.shared.global [%0], [%1], 16;" :: "r"(s), "l"(g));
}
#define CP_COMMIT() asm volatile("cp.async.commit_group;" ::: "memory")
#define CP_WAIT(n)  asm volatile("cp.async.wait_group %0;" :: "n"(n) : "memory")

__device__ __forceinline__ void ldsm4(uint32_t* r, uint32_t addr) {
    asm volatile("ldmatrix.sync.aligned.m8n8.x4.shared.b16 {%0,%1,%2,%3}, [%4];"
                 : "=r"(r[0]), "=r"(r[1]), "=r"(r[2]), "=r"(r[3]) : "r"(addr));
}
__device__ __forceinline__ void mma16816(float* d, const uint32_t* a, const uint32_t* b) {
    asm volatile("mma.sync.aligned.m16n8k16.row.col.f32.bf16.bf16.f32 "
                 "{%0,%1,%2,%3}, {%4,%5,%6,%7}, {%8,%9}, {%0,%1,%2,%3};"
                 : "+f"(d[0]), "+f"(d[1]), "+f"(d[2]), "+f"(d[3])
                 : "r"(a[0]), "r"(a[1]), "r"(a[2]), "r"(a[3]), "r"(b[0]), "r"(b[1]));
}

__device__ __forceinline__ void split_bf16(float v, __nv_bfloat16& hi, __nv_bfloat16& lo) {
    hi = __float2bfloat16(v);
    lo = __float2bfloat16(v - __bfloat162float(hi));
}

// ---------------- all-weights transpose + split (single launch) ----------------
// in[K,N] -> out[N,K] hi/lo, 32x32 tiles.
__global__ __launch_bounds__(256)
void wsplit_all(const float* __restrict__ Wq, const float* __restrict__ Wk,
                const float* __restrict__ Wv, const float* __restrict__ Wo,
                const float* __restrict__ W1, const float* __restrict__ W2,
                __nv_bfloat16* qh, __nv_bfloat16* ql, __nv_bfloat16* kh, __nv_bfloat16* kl,
                __nv_bfloat16* vh, __nv_bfloat16* vl, __nv_bfloat16* oh_, __nv_bfloat16* ol_,
                __nv_bfloat16* f1h, __nv_bfloat16* f1l, __nv_bfloat16* f2h, __nv_bfloat16* f2l)
{
    int t = blockIdx.x;
    int layer = t / 3072, r = t % 3072;
    const float* in; __nv_bfloat16 *oh, *ol;
    int K, N, nx, ky;
    if (r < 1024) {
        int type = r >> 8, tt = r & 255;
        nx = tt & 15; ky = tt >> 4; K = DM; N = DM;
        long off = (long)layer * DM * DM;
        if (type == 0)      { in = Wq + off; oh = qh + off;  ol = ql + off;  }
        else if (type == 1) { in = Wk + off; oh = kh + off;  ol = kl + off;  }
        else if (type == 2) { in = Wv + off; oh = vh + off;  ol = vl + off;  }
        else                { in = Wo + off; oh = oh_ + off; ol = ol_ + off; }
    } else if (r < 2048) {
        int tt = r - 1024;
        nx = tt & 63; ky = tt >> 6; K = DM; N = DFF;
        long off = (long)layer * DM * DFF;
        in = W1 + off; oh = f1h + off; ol = f1l + off;
    } else {
        int tt = r - 2048;
        nx = tt & 15; ky = tt >> 4; K = DFF; N = DM;
        long off = (long)layer * DFF * DM;
        in = W2 + off; oh = f2h + off; ol = f2l + off;
    }

    __shared__ float s[32][33];
    int n0 = nx * 32, k0 = ky * 32;
    int tx = threadIdx.x & 31, ty = threadIdx.x >> 5;
#pragma unroll
    for (int rr = 0; rr < 32; rr += 8)
        s[rr + ty][tx] = in[(size_t)(k0 + rr + ty) * N + n0 + tx];
    __syncthreads();
#pragma unroll
    for (int rr = 0; rr < 32; rr += 8) {
        float v = s[tx][rr + ty];
        __nv_bfloat16 hi, lo; split_bf16(v, hi, lo);
        size_t o = (size_t)(n0 + rr + ty) * K + k0 + tx;
        oh[o] = hi; ol[o] = lo;
    }
}

// ---------------- HMMA bf16-split GEMM ----------------
// C[M,N] = A[M,K]@B[N,K]^T + bias. mode 0: fp32 out. mode 1: relu + split-bf16 out.
#define GS_TILE   10240
#define GS_BUF    40960
#define MMA_SMEM  (2 * GS_BUF)

__global__ __launch_bounds__(256, 2)
void mma_gemm(const __nv_bfloat16* __restrict__ Ah, const __nv_bfloat16* __restrict__ Al,
              const __nv_bfloat16* __restrict__ Bh, const __nv_bfloat16* __restrict__ Bl,
              const float* __restrict__ bias, float* __restrict__ C,
              __nv_bfloat16* __restrict__ Ch, __nv_bfloat16* __restrict__ Cl,
              int N, int K, int mode)
{
    extern __shared__ char smraw[];
    uint32_t sb = smem_u32(smraw);

    int tid = threadIdx.x;
    int l = tid & 31, w = tid >> 5;
    int wm = w >> 1, wn = w & 1;
    int bn = blockIdx.x << 7, bm = blockIdx.y << 7;
    size_t rowb = (size_t)K * 2;

    const char* gAh = (const char*)Ah + (size_t)bm * rowb;
    const char* gAl = (const char*)Al + (size_t)bm * rowb;
    const char* gBh = (const char*)Bh + (size_t)bn * rowb;
    const char* gBl = (const char*)Bl + (size_t)bn * rowb;

    float d[2][8][4];
#pragma unroll
    for (int i = 0; i < 2; i++)
#pragma unroll
        for (int j = 0; j < 8; j++)
#pragma unroll
            for (int t = 0; t < 4; t++) d[i][j][t] = 0.f;

    uint32_t aoff = (uint32_t)((wm * 32 + (l & 7) + ((l >> 3) & 1) * 8) * 80 + ((l >> 4) & 1) * 16);
    uint32_t boff = (uint32_t)((wn * 64 + (l & 7) + ((l >> 4) & 1) * 8) * 80 + ((l >> 3) & 1) * 16);

    const int S = K >> 5;
    int lrow0 = tid >> 2,         lch0 = tid & 3;
    int lrow1 = (tid + 256) >> 2, lch1 = (tid + 256) & 3;

#define LOAD_STAGE(stg, buf) do { \
    size_t go0 = (size_t)lrow0 * rowb + (size_t)(stg) * 64 + lch0 * 16; \
    size_t go1 = (size_t)lrow1 * rowb + (size_t)(stg) * 64 + lch1 * 16; \
    uint32_t so0 = sb + (buf) * GS_BUF + lrow0 * 80 + lch0 * 16; \
    uint32_t so1 = sb + (buf) * GS_BUF + lrow1 * 80 + lch1 * 16; \
    cpa16(so0,               gAh + go0); \
    cpa16(so0 + GS_TILE,     gAl + go0); \
    cpa16(so0 + 2 * GS_TILE, gBh + go0); \
    cpa16(so0 + 3 * GS_TILE, gBl + go0); \
    cpa16(so1,               gAh + go1); \
    cpa16(so1 + GS_TILE,     gAl + go1); \
    cpa16(so1 + 2 * GS_TILE, gBh + go1); \
    cpa16(so1 + 3 * GS_TILE, gBl + go1); \
} while (0)

    LOAD_STAGE(0, 0);
    CP_COMMIT();

    for (int s = 0; s < S; s++) {
        int p = s & 1;
        if (s + 1 < S) {
            LOAD_STAGE(s + 1, p ^ 1);
            CP_COMMIT();
            CP_WAIT(1);
        } else {
            CP_WAIT(0);
        }
        __syncthreads();

        uint32_t bufo = sb + p * GS_BUF;
#pragma unroll
        for (int kk = 0; kk < 2; kk++) {
            uint32_t kb = kk * 32;
            uint32_t ahf[2][4], alf[2][4];
            ldsm4(ahf[0], bufo + aoff + kb);
            ldsm4(ahf[1], bufo + aoff + 1280 + kb);
            ldsm4(alf[0], bufo + GS_TILE + aoff + kb);
            ldsm4(alf[1], bufo + GS_TILE + aoff + 1280 + kb);
#pragma unroll
            for (int n2 = 0; n2 < 4; n2++) {
                uint32_t bh[4], blo[4];
                ldsm4(bh,  bufo + 2 * GS_TILE + boff + n2 * 1280 + kb);
                ldsm4(blo, bufo + 3 * GS_TILE + boff + n2 * 1280 + kb);
#pragma unroll
                for (int mt = 0; mt < 2; mt++) {
                    mma16816(d[mt][n2 * 2 + 0], ahf[mt], bh);
                    mma16816(d[mt][n2 * 2 + 1], ahf[mt], bh + 2);
                    mma16816(d[mt][n2 * 2 + 0], alf[mt], bh);
                    mma16816(d[mt][n2 * 2 + 1], alf[mt], bh + 2);
                    mma16816(d[mt][n2 * 2 + 0], ahf[mt], blo);
                    mma16816(d[mt][n2 * 2 + 1], ahf[mt], blo + 2);
                }
            }
        }
        __syncthreads();
    }

    // ---- epilogue ----
#pragma unroll
    for (int mt = 0; mt < 2; mt++) {
        int r0 = bm + wm * 32 + mt * 16 + (l >> 2);
        int r1 = r0 + 8;
#pragma unroll
        for (int nt = 0; nt < 8; nt++) {
            int c = bn + wn * 64 + nt * 8 + (l & 3) * 2;
            float b0 = bias[c], b1 = bias[c + 1];
            float v0 = d[mt][nt][0] + b0, v1 = d[mt][nt][1] + b1;
            float v2 = d[mt][nt][2] + b0, v3 = d[mt][nt][3] + b1;
            if (mode == 0) {
                if (r0 < BL) { float2 t = {v0, v1}; *(float2*)&C[(size_t)r0 * N + c] = t; }
                if (r1 < BL) { float2 t = {v2, v3}; *(float2*)&C[(size_t)r1 * N + c] = t; }
            } else {
                v0 = fmaxf(v0, 0.f); v1 = fmaxf(v1, 0.f);
                v2 = fmaxf(v2, 0.f); v3 = fmaxf(v3, 0.f);
                __nv_bfloat16 h0, l0_, h1, l1_;
                if (r0 < BL) {
                    split_bf16(v0, h0, l0_); split_bf16(v1, h1, l1_);
                    __nv_bfloat162 hh; hh.x = h0; hh.y = h1;
                    __nv_bfloat162 ll; ll.x = l0_; ll.y = l1_;
                    *(__nv_bfloat162*)&Ch[(size_t)r0 * N + c] = hh;
                    *(__nv_bfloat162*)&Cl[(size_t)r0 * N + c] = ll;
                }
                if (r1 < BL) {
                    split_bf16(v2, h0, l0_); split_bf16(v3, h1, l1_);
                    __nv_bfloat162 hh; hh.x = h0; hh.y = h1;
                    __nv_bfloat162 ll; ll.x = l0_; ll.y = l1_;
                    *(__nv_bfloat162*)&Ch[(size_t)r1 * N + c] = hh;
                    *(__nv_bfloat162*)&Cl[(size_t)r1 * N + c] = ll;
                }
            }
        }
    }
}

// ---------------- embed: h = x @ emb_w + emb_b + pe[l], + split out ----------------
__global__ __launch_bounds__(128)
void embed_kernel(const float* __restrict__ x, const float* __restrict__ ew,
                  const float* __restrict__ eb, const float* __restrict__ pe,
                  float* __restrict__ h, __nv_bfloat16* __restrict__ ah,
                  __nv_bfloat16* __restrict__ al)
{
    __shared__ float sx[7];
    int row = blockIdx.x;
    int l   = row % LSEQ;
    int tid = threadIdx.x;
    if (tid < 7) sx[tid] = x[row * 7 + tid];
    __syncthreads();
    for (int d = tid; d < DM; d += 128) {
        float a = eb[d] + pe[l * DM + d];
#pragma unroll
        for (int f = 0; f < 7; f++) a += sx[f] * ew[f * DM + d];
        h[(long)row * DM + d] = a;
        __nv_bfloat16 hi, lo; split_bf16(a, hi, lo);
        ah[(long)row * DM + d] = hi;
        al[(long)row * DM + d] = lo;
    }
}

// ---------------- learned-mask projection ----------------
__global__ __launch_bounds__(128)
void lmproj_kernel(const float* __restrict__ q, const float* __restrict__ w,
                   const float* __restrict__ b, float* __restrict__ o)
{
    __shared__ float sw[64 * 16];
    __shared__ float sq[8 * 64];
    int tid = threadIdx.x;
    int r0  = blockIdx.x * 8;
    for (int i = tid; i < 1024; i += 128) sw[i] = w[i];
    for (int i = tid; i < 512;  i += 128) sq[i] = q[(long)r0 * 64 + i];
    __syncthreads();
    int rr = tid >> 4, p = tid & 15;
    float a = b[p];
#pragma unroll
    for (int d = 0; d < 64; d++) a += sq[rr * 64 + d] * sw[d * 16 + p];
    o[(long)(r0 + rr) * 16 + p] = a;
}

// ---------------- fused attention (fp32), split-bf16 ctx output ----------------
__device__ __forceinline__ float fast_tanh(float x)
{
    x = fminf(fmaxf(x, -15.f), 15.f);
    float e = __expf(2.f * x);
    return (e - 1.f) / (e + 1.f);
}

#define ATT_SMEM (19008 * 4)

__global__ __launch_bounds__(256)
void attn_kernel(const float* __restrict__ q, const float* __restrict__ kkg,
                 const float* __restrict__ vvg, const float* __restrict__ qp,
                 const float* __restrict__ kp,
                 __nv_bfloat16* __restrict__ ch, __nv_bfloat16* __restrict__ cl)
{
    extern __shared__ float smem[];
    float* sQ   = smem;
    float* sK   = sQ + 4160;
    float* sV   = sK + 4160;
    float* sS   = sV + 4160;
    float* sQP  = sS + 4160;
    float* sKP  = sQP + 1088;
    float* sM   = sKP + 1088;
    float* sSum = sM + 64;
    float* sF   = sSum + 64;

    int tid = threadIdx.x;
    int bid = blockIdx.x;
    int qt = bid & 15;
    int h  = (bid >> 4) & 7;
    int b  = bid >> 7;
    int l0 = qt << 6;

    for (int i = tid; i < 64 * 64; i += 256) {
        int r = i >> 6, d = i & 63;
        int l = l0 + r;
        sQ[r * 65 + d] = (l < LSEQ) ? q[(((b * LSEQ + l) * NH + h) << 6) + d] : 0.f;
    }
    for (int i = tid; i < 64 * 16; i += 256) {
        int r = i >> 4, p = i & 15;
        int l = l0 + r;
        sQP[r * 17 + p] = (l < LSEQ) ? qp[(((b * LSEQ + l) * NH + h) << 4) + p] : 0.f;
    }
    if (tid < 64) { sM[tid] = -1e30f; sSum[tid] = 0.f; }

    int ty = tid >> 4, tx = tid & 15;
    float acc[4][4];
#pragma unroll
    for (int i = 0; i < 4; i++)
#pragma unroll
        for (int j = 0; j < 4; j++) acc[i][j] = 0.f;

    __syncthreads();

    for (int st = 0; st < 16; st++) {
        int s0 = st << 6;
        for (int i = tid; i < 64 * 64; i += 256) {
            int r = i >> 6, d = i & 63;
            int s = s0 + r;
            if (s < LSEQ) {
                int gi = (((b * LSEQ + s) * NH + h) << 6) + d;
                sK[r * 65 + d] = kkg[gi];
                sV[r * 65 + d] = vvg[gi];
            } else { sK[r * 65 + d] = 0.f; sV[r * 65 + d] = 0.f; }
        }
        for (int i = tid; i < 64 * 16; i += 256) {
            int r = i >> 4, p = i & 15;
            int s = s0 + r;
            sKP[r * 17 + p] = (s < LSEQ) ? kp[(((b * LSEQ + s) * NH + h) << 4) + p] : 0.f;
        }
        __syncthreads();

        float sc[4][4], scp[4][4];
#pragma unroll
        for (int i = 0; i < 4; i++)
#pragma unroll
            for (int j = 0; j < 4; j++) { sc[i][j] = 0.f; scp[i][j] = 0.f; }

        for (int d = 0; d < 64; d++) {
            float aq[4], bk[4];
#pragma unroll
            for (int i = 0; i < 4; i++) aq[i] = sQ[(ty * 4 + i) * 65 + d];
#pragma unroll
            for (int j = 0; j < 4; j++) bk[j] = sK[(tx * 4 + j) * 65 + d];
#pragma unroll
            for (int i = 0; i < 4; i++)
#pragma unroll
                for (int j = 0; j < 4; j++) sc[i][j] += aq[i] * bk[j];
        }
#pragma unroll
        for (int p = 0; p < 16; p++) {
            float aq[4], bk[4];
#pragma unroll
            for (int i = 0; i < 4; i++) aq[i] = sQP[(ty * 4 + i) * 17 + p];
#pragma unroll
            for (int j = 0; j < 4; j++) bk[j] = sKP[(tx * 4 + j) * 17 + p];
#pragma unroll
            for (int i = 0; i < 4; i++)
#pragma unroll
                for (int j = 0; j < 4; j++) scp[i][j] += aq[i] * bk[j];
        }
#pragma unroll
        for (int i = 0; i < 4; i++)
#pragma unroll
            for (int j = 0; j < 4; j++)
                sS[(ty * 4 + i) * 65 + tx * 4 + j] = sc[i][j] * 0.125f + fast_tanh(scp[i][j]);
        __syncthreads();

        int qr = tid >> 2, part = tid & 3;
        float mold = sM[qr];
        float mx = mold;
#pragma unroll
        for (int t = 0; t < 16; t++) {
            int s = (part << 4) + t;
            float val = (s0 + s < LSEQ) ? sS[qr * 65 + s] : -1e30f;
            mx = fmaxf(mx, val);
        }
        mx = fmaxf(mx, __shfl_xor_sync(0xffffffffu, mx, 1));
        mx = fmaxf(mx, __shfl_xor_sync(0xffffffffu, mx, 2));
        float psum = 0.f;
#pragma unroll
        for (int t = 0; t < 16; t++) {
            int s = (part << 4) + t;
            float val = (s0 + s < LSEQ) ? sS[qr * 65 + s] : -1e30f;
            float pv = __expf(val - mx);
            sS[qr * 65 + s] = pv;
            psum += pv;
        }
        psum += __shfl_xor_sync(0xffffffffu, psum, 1);
        psum += __shfl_xor_sync(0xffffffffu, psum, 2);
        if (part == 0) {
            float factor = __expf(mold - mx);
            sSum[qr] = sSum[qr] * factor + psum;
            sM[qr]   = mx;
            sF[qr]   = factor;
        }
        __syncthreads();

        float fr[4];
#pragma unroll
        for (int i = 0; i < 4; i++) fr[i] = sF[ty * 4 + i];
#pragma unroll
        for (int i = 0; i < 4; i++)
#pragma unroll
            for (int j = 0; j < 4; j++) acc[i][j] *= fr[i];

        for (int s = 0; s < 64; s++) {
            float pq[4], vr[4];
#pragma unroll
            for (int i = 0; i < 4; i++) pq[i] = sS[(ty * 4 + i) * 65 + s];
#pragma unroll
            for (int j = 0; j < 4; j++) vr[j] = sV[s * 65 + tx * 4 + j];
#pragma unroll
            for (int i = 0; i < 4; i++)
#pragma unroll
                for (int j = 0; j < 4; j++) acc[i][j] += pq[i] * vr[j];
        }
        __syncthreads();
    }

    float rs[4];
#pragma unroll
    for (int i = 0; i < 4; i++) rs[i] = 1.f / sSum[ty * 4 + i];
#pragma unroll
    for (int i = 0; i < 4; i++) {
        int l = l0 + ty * 4 + i;
        if (l < LSEQ) {
#pragma unroll
            for (int j = 0; j < 4; j++) {
                float v = acc[i][j] * rs[i];
                __nv_bfloat16 hi, lo; split_bf16(v, hi, lo);
                size_t o = (size_t)(b * LSEQ + l) * DM + h * DKH + tx * 4 + j;
                ch[o] = hi; cl[o] = lo;
            }
        }
    }
}

// ---------------- LayerNorm (+ optional split out) ----------------
__global__ __launch_bounds__(128)
void ln_kernel(float* __restrict__ out, const float* __restrict__ a,
               const float* __restrict__ y, const float* __restrict__ g,
               const float* __restrict__ bb,
               __nv_bfloat16* __restrict__ oh, __nv_bfloat16* __restrict__ ol)
{
    int row = blockIdx.x, tid = threadIdx.x;
    float4 v = ((const float4*)(a + (long)row * DM))[tid];
    if (y) {
        float4 vy = ((const float4*)(y + (long)row * DM))[tid];
        v.x += vy.x; v.y += vy.y; v.z += vy.z; v.w += vy.w;
    }
    float s  = v.x + v.y + v.z + v.w;
    float sq = v.x * v.x + v.y * v.y + v.z * v.z + v.w * v.w;
#pragma unroll
    for (int o = 16; o > 0; o >>= 1) {
        s  += __shfl_xor_sync(0xffffffffu, s,  o);
        sq += __shfl_xor_sync(0xffffffffu, sq, o);
    }
    __shared__ float shs[4], shq[4];
    int wid = tid >> 5;
    if ((tid & 31) == 0) { shs[wid] = s; shq[wid] = sq; }
    __syncthreads();
    s  = shs[0] + shs[1] + shs[2] + shs[3];
    sq = shq[0] + shq[1] + shq[2] + shq[3];
    float mean = s * (1.f / DM);
    float var  = sq * (1.f / DM) - mean * mean;
    float rstd = rsqrtf(var + 1e-5f);
    float4 gg = ((const float4*)g)[tid];
    float4 bv = ((const float4*)bb)[tid];
    float4 o4;
    o4.x = (v.x - mean) * rstd * gg.x + bv.x;
    o4.y = (v.y - mean) * rstd * gg.y + bv.y;
    o4.z = (v.z - mean) * rstd * gg.z + bv.z;
    o4.w = (v.w - mean) * rstd * gg.w + bv.w;
    ((float4*)(out + (long)row * DM))[tid] = o4;
    if (oh) {
        __nv_bfloat16 h0, l0, h1, l1, h2, l2, h3, l3;
        split_bf16(o4.x, h0, l0); split_bf16(o4.y, h1, l1);
        split_bf16(o4.z, h2, l2); split_bf16(o4.w, h3, l3);
        __nv_bfloat162 hh0; hh0.x = h0; hh0.y = h1;
        __nv_bfloat162 hh1; hh1.x = h2; hh1.y = h3;
        __nv_bfloat162 ll0; ll0.x = l0; ll0.y = l1;
        __nv_bfloat162 ll1; ll1.x = l2; ll1.y = l3;
        ((__nv_bfloat162*)(oh + (long)row * DM))[tid * 2]     = hh0;
        ((__nv_bfloat162*)(oh + (long)row * DM))[tid * 2 + 1] = hh1;
        ((__nv_bfloat162*)(ol + (long)row * DM))[tid * 2]     = ll0;
        ((__nv_bfloat162*)(ol + (long)row * DM))[tid * 2 + 1] = ll1;
    }
}

// ---------------- final FC on last token ----------------
__global__ __launch_bounds__(64)
void fc_kernel(const float* __restrict__ hin, const float* __restrict__ w,
               const float* __restrict__ b, float* __restrict__ out)
{
    __shared__ float sh[512];
    int tid = threadIdx.x;
    int bb  = blockIdx.x;
    const float* row = hin + ((long)bb * LSEQ + (LSEQ - 1)) * DM;
    for (int i = tid; i < 512; i += 64) sh[i] = row[i];
    __syncthreads();
    if (tid < 50) {
        float a = b[tid];
#pragma unroll 8
        for (int d = 0; d < 512; d++) a += sh[d] * w[d * 50 + tid];
        out[bb * 50 + tid] = a;
    }
}

// ---------------- launch ----------------
extern "C" void kernel_launch(void* const* d_in, const int* in_sizes, int n_in,
                              void* d_out, int out_size)
{
    const float* x     = (const float*)d_in[0];
    const float* emb_w = (const float*)d_in[1];
    const float* emb_b = (const float*)d_in[2];
    const float* pe    = (const float*)d_in[3];
    const float* Wq    = (const float*)d_in[4];
    const float* bq    = (const float*)d_in[5];
    const float* Wk    = (const float*)d_in[6];
    const float* bk    = (const float*)d_in[7];
    const float* Wv    = (const float*)d_in[8];
    const float* bv    = (const float*)d_in[9];
    const float* Wo    = (const float*)d_in[10];
    const float* bo    = (const float*)d_in[11];
    const float* W1    = (const float*)d_in[12];
    const float* b1    = (const float*)d_in[13];
    const float* W2    = (const float*)d_in[14];
    const float* b2    = (const float*)d_in[15];
    const float* g1    = (const float*)d_in[16];
    const float* be1   = (const float*)d_in[17];
    const float* g2    = (const float*)d_in[18];
    const float* be2   = (const float*)d_in[19];
    const float* lm_qw = (const float*)d_in[20];
    const float* lm_qb = (const float*)d_in[21];
    const float* lm_kw = (const float*)d_in[22];
    const float* lm_kb = (const float*)d_in[23];
    const float* gn    = (const float*)d_in[24];
    const float* bn    = (const float*)d_in[25];
    const float* fc_w  = (const float*)d_in[26];
    const float* fc_b  = (const float*)d_in[27];
    float* out = (float*)d_out;

    float *h, *q, *k, *v, *t1, *t2, *qpb, *kpb;
    cudaGetSymbolAddress((void**)&h,   g_h);
    cudaGetSymbolAddress((void**)&q,   g_q);
    cudaGetSymbolAddress((void**)&k,   g_k);
    cudaGetSymbolAddress((void**)&v,   g_v);
    cudaGetSymbolAddress((void**)&t1,  g_t1);
    cudaGetSymbolAddress((void**)&t2,  g_t2);
    cudaGetSymbolAddress((void**)&qpb, g_qp);
    cudaGetSymbolAddress((void**)&kpb, g_kp);

    __nv_bfloat16 *wqh, *wql, *wkh, *wkl, *wvh, *wvl, *woh, *wol;
    __nv_bfloat16 *w1h, *w1l, *w2h, *w2l, *ah, *al, *ffh, *ffl;
    cudaGetSymbolAddress((void**)&wqh, g_wqh);
    cudaGetSymbolAddress((void**)&wql, g_wql);
    cudaGetSymbolAddress((void**)&wkh, g_wkh);
    cudaGetSymbolAddress((void**)&wkl, g_wkl);
    cudaGetSymbolAddress((void**)&wvh, g_wvh);
    cudaGetSymbolAddress((void**)&wvl, g_wvl);
    cudaGetSymbolAddress((void**)&woh, g_woh);
    cudaGetSymbolAddress((void**)&wol, g_wol);
    cudaGetSymbolAddress((void**)&w1h, g_w1h);
    cudaGetSymbolAddress((void**)&w1l, g_w1l);
    cudaGetSymbolAddress((void**)&w2h, g_w2h);
    cudaGetSymbolAddress((void**)&w2l, g_w2l);
    cudaGetSymbolAddress((void**)&ah,  g_ah);
    cudaGetSymbolAddress((void**)&al,  g_al);
    cudaGetSymbolAddress((void**)&ffh, g_ffh);
    cudaGetSymbolAddress((void**)&ffl, g_ffl);

    cudaFuncSetAttribute(attn_kernel, cudaFuncAttributeMaxDynamicSharedMemorySize, ATT_SMEM);
    cudaFuncSetAttribute(mma_gemm,    cudaFuncAttributeMaxDynamicSharedMemorySize, MMA_SMEM);

    // launch 0: all weight splits in one kernel
    wsplit_all<<<NL * 3072, 256>>>(Wq, Wk, Wv, Wo, W1, W2,
                                   wqh, wql, wkh, wkl, wvh, wvl, woh, wol,
                                   w1h, w1l, w2h, w2l);
    // launch 1: embed (+ split)
    embed_kernel<<<BL, 128>>>(x, emb_w, emb_b, pe, h, ah, al);

    const int MT = MPAD / 128;
    dim3 gq(DM / 128, MT);
    dim3 gf1(DFF / 128, MT);

    for (int i = 0; i < NL; i++) {
        long o512 = (long)i * DM * DM;
        long offf = (long)i * DM * DFF;

        // launches 2,3: Q,K; 4: lmproj(q); 5: V (ncu -s 5 -c 1 lands here on layer 0)
        mma_gemm<<<gq, 256, MMA_SMEM>>>(ah, al, wqh + o512, wql + o512, bq + i * DM, q,
                                        (__nv_bfloat16*)0, (__nv_bfloat16*)0, DM, DM, 0);
        mma_gemm<<<gq, 256, MMA_SMEM>>>(ah, al, wkh + o512, wkl + o512, bk + i * DM, k,
                                        (__nv_bfloat16*)0, (__nv_bfloat16*)0, DM, DM, 0);
        lmproj_kernel<<<BL, 128>>>(q, lm_qw, lm_qb, qpb);
        mma_gemm<<<gq, 256, MMA_SMEM>>>(ah, al, wvh + o512, wvl + o512, bv + i * DM, v,
                                        (__nv_bfloat16*)0, (__nv_bfloat16*)0, DM, DM, 0);
        lmproj_kernel<<<BL, 128>>>(k, lm_kw, lm_kb, kpb);

        attn_kernel<<<NB * NH * 16, 256, ATT_SMEM>>>(q, k, v, qpb, kpb, ah, al);

        mma_gemm<<<gq, 256, MMA_SMEM>>>(ah, al, woh + o512, wol + o512, bo + i * DM, t1,
                                        (__nv_bfloat16*)0, (__nv_bfloat16*)0, DM, DM, 0);
        ln_kernel<<<BL, 128>>>(h, h, t1, g1 + i * DM, be1 + i * DM, ah, al);

        mma_gemm<<<gf1, 256, MMA_SMEM>>>(ah, al, w1h + offf, w1l + offf, b1 + i * DFF,
                                         (float*)0, ffh, ffl, DFF, DM, 1);
        mma_gemm<<<gq, 256, MMA_SMEM>>>(ffh, ffl, w2h + offf, w2l + offf, b2 + i * DM, t2,
                                        (__nv_bfloat16*)0, (__nv_bfloat16*)0, DM, DFF, 0);

        ln_kernel<<<BL, 128>>>(t1, h, t2, g2 + i * DM, be2 + i * DM,
                               (__nv_bfloat16*)0, (__nv_bfloat16*)0);
        ln_kernel<<<BL, 128>>>(h, t1, t2, g2 + i * DM, be2 + i * DM, ah, al);
    }

    ln_kernel<<<BL, 128>>>(t1, h, (const float*)nullptr, gn, bn,
                           (__nv_bfloat16*)0, (__nv_bfloat16*)0);
    fc_kernel<<<NB, 64>>>(t1, fc_w, fc_b, out);
}

// round 10
// speedup vs baseline: 2.0743x; 1.2150x over previous
#include <cuda_runtime.h>
#include <cuda_bf16.h>
#include <math.h>
#include <stdint.h>

#define BL    8000
#define MPAD  8064
#define DM    512
#define DFF   2048
#define NL    4
#define LSEQ  1000
#define NB    8
#define NH    8
#define DKH   64
#define PP    16

// ---------------- scratch (device globals; no allocation allowed) ----------------
__device__ float g_h  [BL * DM];
__device__ float g_t1 [BL * DM];
__device__ float g_t2 [BL * DM];

// bf16 split weight buffers (transposed to [N,K])
__device__ __nv_bfloat16 g_wqh[NL * DM * DM];
__device__ __nv_bfloat16 g_wql[NL * DM * DM];
__device__ __nv_bfloat16 g_wkh[NL * DM * DM];
__device__ __nv_bfloat16 g_wkl[NL * DM * DM];
__device__ __nv_bfloat16 g_wvh[NL * DM * DM];
__device__ __nv_bfloat16 g_wvl[NL * DM * DM];
__device__ __nv_bfloat16 g_woh[NL * DM * DM];
__device__ __nv_bfloat16 g_wol[NL * DM * DM];
__device__ __nv_bfloat16 g_w1h[NL * DM * DFF];
__device__ __nv_bfloat16 g_w1l[NL * DM * DFF];
__device__ __nv_bfloat16 g_w2h[NL * DFF * DM];
__device__ __nv_bfloat16 g_w2l[NL * DFF * DM];
// bf16 split activation buffers
__device__ __nv_bfloat16 g_ah [MPAD * DM];
__device__ __nv_bfloat16 g_al [MPAD * DM];
__device__ __nv_bfloat16 g_ffh[MPAD * DFF];
__device__ __nv_bfloat16 g_ffl[MPAD * DFF];
// split qkv
__device__ __nv_bfloat16 g_qh [MPAD * DM];
__device__ __nv_bfloat16 g_ql [MPAD * DM];
__device__ __nv_bfloat16 g_kh [MPAD * DM];
__device__ __nv_bfloat16 g_kl [MPAD * DM];
__device__ __nv_bfloat16 g_vh [MPAD * DM];
__device__ __nv_bfloat16 g_vl [MPAD * DM];
// learned-mask projections (bf16)
__device__ __nv_bfloat16 g_qp [BL * NH * PP];
__device__ __nv_bfloat16 g_kp [BL * NH * PP];

// ================= PTX helpers (baseline ISA only) =================
__device__ __forceinline__ uint32_t smem_u32(const void* p) {
    uint32_t a;
    asm("{ .reg .u64 t; cvta.to.shared.u64 t, %1; cvt.u32.u64 %0, t; }" : "=r"(a) : "l"(p));
    return a;
}
__device__ __forceinline__ void cpa16(uint32_t s, const void* g) {
    asm volatile("cp.async.cg.shared.global [%0], [%1], 16;" :: "r"(s), "l"(g));
}
__device__ __forceinline__ void cpa16z(uint32_t s, const void* g, int sz) {
    asm volatile("cp.async.cg.shared.global [%0], [%1], 16, %2;" :: "r"(s), "l"(g), "r"(sz));
}
#define CP_COMMIT() asm volatile("cp.async.commit_group;" ::: "memory")
#define CP_WAIT(n)  asm volatile("cp.async.wait_group %0;" :: "n"(n) : "memory")

__device__ __forceinline__ void ldsm4(uint32_t* r, uint32_t addr) {
    asm volatile("ldmatrix.sync.aligned.m8n8.x4.shared.b16 {%0,%1,%2,%3}, [%4];"
                 : "=r"(r[0]), "=r"(r[1]), "=r"(r[2]), "=r"(r[3]) : "r"(addr));
}
__device__ __forceinline__ void ldsm4t(uint32_t* r, uint32_t addr) {
    asm volatile("ldmatrix.sync.aligned.m8n8.x4.trans.shared.b16 {%0,%1,%2,%3}, [%4];"
                 : "=r"(r[0]), "=r"(r[1]), "=r"(r[2]), "=r"(r[3]) : "r"(addr));
}
__device__ __forceinline__ void mma16816(float* d, const uint32_t* a, const uint32_t* b) {
    asm volatile("mma.sync.aligned.m16n8k16.row.col.f32.bf16.bf16.f32 "
                 "{%0,%1,%2,%3}, {%4,%5,%6,%7}, {%8,%9}, {%0,%1,%2,%3};"
                 : "+f"(d[0]), "+f"(d[1]), "+f"(d[2]), "+f"(d[3])
                 : "r"(a[0]), "r"(a[1]), "r"(a[2]), "r"(a[3]), "r"(b[0]), "r"(b[1]));
}
__device__ __forceinline__ float tanh_fast(float x) {
    float r;
    asm("tanh.approx.f32 %0, %1;" : "=f"(r) : "f"(x));
    return r;
}
__device__ __forceinline__ void split_bf16(float v, __nv_bfloat16& hi, __nv_bfloat16& lo) {
    hi = __float2bfloat16(v);
    lo = __float2bfloat16(v - __bfloat162float(hi));
}
__device__ __forceinline__ uint32_t pack_hi(float a, float b) {
    __nv_bfloat162 h; h.x = __float2bfloat16(a); h.y = __float2bfloat16(b);
    return *(uint32_t*)&h;
}
__device__ __forceinline__ uint32_t pack_lo(float a, float b) {
    __nv_bfloat16 ha = __float2bfloat16(a), hb = __float2bfloat16(b);
    __nv_bfloat162 h;
    h.x = __float2bfloat16(a - __bfloat162float(ha));
    h.y = __float2bfloat16(b - __bfloat162float(hb));
    return *(uint32_t*)&h;
}

// ---------------- all-weights transpose + split (single launch) ----------------
__global__ __launch_bounds__(256)
void wsplit_all(const float* __restrict__ Wq, const float* __restrict__ Wk,
                const float* __restrict__ Wv, const float* __restrict__ Wo,
                const float* __restrict__ W1, const float* __restrict__ W2,
                __nv_bfloat16* qh, __nv_bfloat16* ql, __nv_bfloat16* kh, __nv_bfloat16* kl,
                __nv_bfloat16* vh, __nv_bfloat16* vl, __nv_bfloat16* oh_, __nv_bfloat16* ol_,
                __nv_bfloat16* f1h, __nv_bfloat16* f1l, __nv_bfloat16* f2h, __nv_bfloat16* f2l)
{
    int t = blockIdx.x;
    int layer = t / 3072, r = t % 3072;
    const float* in; __nv_bfloat16 *oh, *ol;
    int K, N, nx, ky;
    if (r < 1024) {
        int type = r >> 8, tt = r & 255;
        nx = tt & 15; ky = tt >> 4; K = DM; N = DM;
        long off = (long)layer * DM * DM;
        if (type == 0)      { in = Wq + off; oh = qh + off;  ol = ql + off;  }
        else if (type == 1) { in = Wk + off; oh = kh + off;  ol = kl + off;  }
        else if (type == 2) { in = Wv + off; oh = vh + off;  ol = vl + off;  }
        else                { in = Wo + off; oh = oh_ + off; ol = ol_ + off; }
    } else if (r < 2048) {
        int tt = r - 1024;
        nx = tt & 63; ky = tt >> 6; K = DM; N = DFF;
        long off = (long)layer * DM * DFF;
        in = W1 + off; oh = f1h + off; ol = f1l + off;
    } else {
        int tt = r - 2048;
        nx = tt & 15; ky = tt >> 4; K = DFF; N = DM;
        long off = (long)layer * DFF * DM;
        in = W2 + off; oh = f2h + off; ol = f2l + off;
    }

    __shared__ float s[32][33];
    int n0 = nx * 32, k0 = ky * 32;
    int tx = threadIdx.x & 31, ty = threadIdx.x >> 5;
#pragma unroll
    for (int rr = 0; rr < 32; rr += 8)
        s[rr + ty][tx] = in[(size_t)(k0 + rr + ty) * N + n0 + tx];
    __syncthreads();
#pragma unroll
    for (int rr = 0; rr < 32; rr += 8) {
        float v = s[tx][rr + ty];
        __nv_bfloat16 hi, lo; split_bf16(v, hi, lo);
        size_t o = (size_t)(n0 + rr + ty) * K + k0 + tx;
        oh[o] = hi; ol[o] = lo;
    }
}

// ---------------- HMMA bf16-split GEMM (XOR-swizzled smem) ----------------
// Stage tile: A[128 rows x 128B] (chunks 0-3 = hi k0..31, 4-7 = lo), B same.
// mode bits: 1=relu, 2=write fp32 C, 4=write split Ch/Cl.
#define GST       16384
#define GSTAGE    32768
#define MMA_SMEM  (2 * GSTAGE)

__global__ __launch_bounds__(256, 2)
void mma_gemm(const __nv_bfloat16* __restrict__ Ah, const __nv_bfloat16* __restrict__ Al,
              const __nv_bfloat16* __restrict__ Bh, const __nv_bfloat16* __restrict__ Bl,
              const float* __restrict__ bias, float* __restrict__ C,
              __nv_bfloat16* __restrict__ Ch, __nv_bfloat16* __restrict__ Cl,
              int N, int K, int mode)
{
    extern __shared__ char smraw[];
    uint32_t sb = smem_u32(smraw);

    int tid = threadIdx.x;
    int l = tid & 31, w = tid >> 5;
    int wm = w >> 1, wn = w & 1;
    int bn = blockIdx.x << 7, bm = blockIdx.y << 7;
    size_t rowb = (size_t)K * 2;

    const char* gAh = (const char*)Ah + (size_t)bm * rowb;
    const char* gAl = (const char*)Al + (size_t)bm * rowb;
    const char* gBh = (const char*)Bh + (size_t)bn * rowb;
    const char* gBl = (const char*)Bl + (size_t)bn * rowb;

    float d[2][8][4];
#pragma unroll
    for (int i = 0; i < 2; i++)
#pragma unroll
        for (int j = 0; j < 8; j++)
#pragma unroll
            for (int t = 0; t < 4; t++) d[i][j][t] = 0.f;

    const int S = K >> 5;

#define G_LOAD_STAGE(stg, buf) do { \
    _Pragma("unroll") \
    for (int i = 0; i < 8; i++) { \
        int id = i * 256 + tid; \
        int ab = id >> 10, rem = id & 1023; \
        int row = rem >> 3, c = rem & 7; \
        const char* gh = ab ? gBh : gAh; \
        const char* gl = ab ? gBl : gAl; \
        const char* src = (c < 4 ? gh : gl) + (size_t)row * rowb + (size_t)(stg) * 64 + (c & 3) * 16; \
        uint32_t dst = sb + (buf) * GSTAGE + ab * GST + row * 128 + ((c ^ (row & 7)) << 4); \
        cpa16(dst, src); \
    } \
} while (0)

    G_LOAD_STAGE(0, 0);
    CP_COMMIT();

    for (int s = 0; s < S; s++) {
        int p = s & 1;
        if (s + 1 < S) {
            G_LOAD_STAGE(s + 1, p ^ 1);
            CP_COMMIT();
            CP_WAIT(1);
        } else {
            CP_WAIT(0);
        }
        __syncthreads();

        uint32_t bufo = sb + p * GSTAGE;
#pragma unroll
        for (int kk = 0; kk < 2; kk++) {
            uint32_t ahf[2][4], alf[2][4];
#pragma unroll
            for (int mt = 0; mt < 2; mt++) {
                int ra = wm * 32 + mt * 16 + (l & 15);
                int ca = kk * 2 + ((l >> 4) & 1);
                ldsm4(ahf[mt], bufo + ra * 128 + ((ca ^ (ra & 7)) << 4));
                ldsm4(alf[mt], bufo + ra * 128 + (((ca + 4) ^ (ra & 7)) << 4));
            }
#pragma unroll
            for (int g = 0; g < 4; g++) {
                int rb = wn * 64 + g * 16 + (l & 7) + ((l >> 4) & 1) * 8;
                int cb = kk * 2 + ((l >> 3) & 1);
                uint32_t bh[4], blo[4];
                ldsm4(bh,  bufo + GST + rb * 128 + ((cb ^ (rb & 7)) << 4));
                ldsm4(blo, bufo + GST + rb * 128 + (((cb + 4) ^ (rb & 7)) << 4));
#pragma unroll
                for (int mt = 0; mt < 2; mt++) {
                    mma16816(d[mt][g * 2 + 0], ahf[mt], bh);
                    mma16816(d[mt][g * 2 + 1], ahf[mt], bh + 2);
                    mma16816(d[mt][g * 2 + 0], alf[mt], bh);
                    mma16816(d[mt][g * 2 + 1], alf[mt], bh + 2);
                    mma16816(d[mt][g * 2 + 0], ahf[mt], blo);
                    mma16816(d[mt][g * 2 + 1], ahf[mt], blo + 2);
                }
            }
        }
        __syncthreads();
    }

    // ---- epilogue ----
    bool dorelu = (mode & 1), dof32 = (mode & 2), dosplit = (mode & 4);
#pragma unroll
    for (int mt = 0; mt < 2; mt++) {
        int r0 = bm + wm * 32 + mt * 16 + (l >> 2);
        int r1 = r0 + 8;
#pragma unroll
        for (int nt = 0; nt < 8; nt++) {
            int c = bn + wn * 64 + nt * 8 + (l & 3) * 2;
            float b0 = bias[c], b1 = bias[c + 1];
            float v0 = d[mt][nt][0] + b0, v1 = d[mt][nt][1] + b1;
            float v2 = d[mt][nt][2] + b0, v3 = d[mt][nt][3] + b1;
            if (dorelu) {
                v0 = fmaxf(v0, 0.f); v1 = fmaxf(v1, 0.f);
                v2 = fmaxf(v2, 0.f); v3 = fmaxf(v3, 0.f);
            }
            if (dof32) {
                if (r0 < BL) { float2 t = {v0, v1}; *(float2*)&C[(size_t)r0 * N + c] = t; }
                if (r1 < BL) { float2 t = {v2, v3}; *(float2*)&C[(size_t)r1 * N + c] = t; }
            }
            if (dosplit) {
                if (r0 < BL) {
                    *(uint32_t*)&Ch[(size_t)r0 * N + c] = pack_hi(v0, v1);
                    *(uint32_t*)&Cl[(size_t)r0 * N + c] = pack_lo(v0, v1);
                }
                if (r1 < BL) {
                    *(uint32_t*)&Ch[(size_t)r1 * N + c] = pack_hi(v2, v3);
                    *(uint32_t*)&Cl[(size_t)r1 * N + c] = pack_lo(v2, v3);
                }
            }
        }
    }
}

// ---------------- embed: h = x @ emb_w + emb_b + pe[l], + split out ----------------
__global__ __launch_bounds__(128)
void embed_kernel(const float* __restrict__ x, const float* __restrict__ ew,
                  const float* __restrict__ eb, const float* __restrict__ pe,
                  float* __restrict__ h, __nv_bfloat16* __restrict__ ah,
                  __nv_bfloat16* __restrict__ al)
{
    __shared__ float sx[7];
    int row = blockIdx.x;
    int l   = row % LSEQ;
    int tid = threadIdx.x;
    if (tid < 7) sx[tid] = x[row * 7 + tid];
    __syncthreads();
    for (int d = tid; d < DM; d += 128) {
        float a = eb[d] + pe[l * DM + d];
#pragma unroll
        for (int f = 0; f < 7; f++) a += sx[f] * ew[f * DM + d];
        h[(long)row * DM + d] = a;
        __nv_bfloat16 hi, lo; split_bf16(a, hi, lo);
        ah[(long)row * DM + d] = hi;
        al[(long)row * DM + d] = lo;
    }
}

// ---------------- learned-mask projection (bf16 in / bf16 out) ----------------
__global__ __launch_bounds__(128)
void lmproj_kernel(const __nv_bfloat16* __restrict__ q, const float* __restrict__ w,
                   const float* __restrict__ b, __nv_bfloat16* __restrict__ o)
{
    __shared__ float sw[64 * 16];
    __shared__ float sq[8 * 64];
    int tid = threadIdx.x;
    int r0  = blockIdx.x * 8;
    for (int i = tid; i < 1024; i += 128) sw[i] = w[i];
    for (int i = tid; i < 512;  i += 128) sq[i] = __bfloat162float(q[(long)r0 * 64 + i]);
    __syncthreads();
    int rr = tid >> 4, p = tid & 15;
    float a = b[p];
#pragma unroll
    for (int d = 0; d < 64; d++) a += sq[rr * 64 + d] * sw[d * 16 + p];
    o[(long)(r0 + rr) * 16 + p] = __float2bfloat16(a);
}

// ---------------- tensor-core fused attention ----------------
// Block: 128 threads (4 warps), one (b, h, 64-query tile). Warp w owns q rows 16w..16w+15.
// smem: Q(16KB swz) + QP(3K, 48B-stride rows) + 2 stages of [K 16K | V 16K | KP 3K].
#define SQ_OFF   0
#define SQP_OFF  16384
#define STG_OFF  19456
#define STG_SZ   35840          // K 16384 + V 16384 + KP 3072
#define ATT_SMEM (19456 + 2 * STG_SZ)   // 91136

// swizzled addr in a 64-row x 256B tile (chunks 0-7 hi, 8-15 lo)
#define SWZ(base, row, c) \
    ((base) + (row) * 256 + (((c) < 8) ? (((c) ^ ((row) & 7)) << 4) \
                                       : (128 + ((((c) - 8) ^ ((row) & 7)) << 4))))

__global__ __launch_bounds__(128)
void attn_kernel(const __nv_bfloat16* __restrict__ qh, const __nv_bfloat16* __restrict__ ql,
                 const __nv_bfloat16* __restrict__ kh, const __nv_bfloat16* __restrict__ kl,
                 const __nv_bfloat16* __restrict__ vh, const __nv_bfloat16* __restrict__ vl,
                 const __nv_bfloat16* __restrict__ qp, const __nv_bfloat16* __restrict__ kp,
                 __nv_bfloat16* __restrict__ ch, __nv_bfloat16* __restrict__ cl)
{
    extern __shared__ char smraw[];
    uint32_t sb = smem_u32(smraw);
    int tid = threadIdx.x;
    int l = tid & 31, w = tid >> 5;
    int bid = blockIdx.x;
    int qt = bid & 15;
    int h  = (bid >> 4) & 7;
    int b  = bid >> 7;
    int l0 = qt << 6;

    // ---- load Q (hi+lo) + QP once ----
    {
#pragma unroll
        for (int i = 0; i < 8; i++) {
            int id = i * 128 + tid;
            int row = id >> 4, c = id & 15;
            int lq = l0 + row;
            const __nv_bfloat16* base = (c < 8) ? qh : ql;
            const __nv_bfloat16* src = base + ((size_t)(b * LSEQ + (lq < LSEQ ? lq : 0))) * DM + h * DKH + (c & 7) * 8;
            cpa16z(SWZ(sb + SQ_OFF, row, c), src, lq < LSEQ ? 16 : 0);
        }
        int row = tid >> 1, cc = tid & 1;
        int lq = l0 + row;
        const __nv_bfloat16* src = qp + ((size_t)((b * LSEQ + (lq < LSEQ ? lq : 0)) * NH + h)) * PP + cc * 8;
        cpa16z(sb + SQP_OFF + row * 48 + cc * 16, src, lq < LSEQ ? 16 : 0);
    }

#define A_LOAD_STAGE(st, buf) do { \
    uint32_t so = sb + STG_OFF + (buf) * STG_SZ; \
    _Pragma("unroll") \
    for (int i = 0; i < 8; i++) { \
        int id = i * 128 + tid; \
        int row = id >> 4, c = id & 15; \
        int s = (st) * 64 + row; \
        int ok = (s < LSEQ) ? 16 : 0; \
        size_t go = ((size_t)(b * LSEQ + (s < LSEQ ? s : 0))) * DM + h * DKH + (c & 7) * 8; \
        cpa16z(SWZ(so, row, c),         ((c < 8) ? kh : kl) + go, ok); \
        cpa16z(SWZ(so + 16384, row, c), ((c < 8) ? vh : vl) + go, ok); \
    } \
    { \
        int row = tid >> 1, cc = tid & 1; \
        int s = (st) * 64 + row; \
        const __nv_bfloat16* src = kp + ((size_t)((b * LSEQ + (s < LSEQ ? s : 0)) * NH + h)) * PP + cc * 8; \
        cpa16z(so + 32768 + row * 48 + cc * 16, src, s < LSEQ ? 16 : 0); \
    } \
} while (0)

    A_LOAD_STAGE(0, 0);
    CP_COMMIT();

    // state
    float o[8][4];
#pragma unroll
    for (int i = 0; i < 8; i++)
#pragma unroll
        for (int j = 0; j < 4; j++) o[i][j] = 0.f;
    float m0 = -1e30f, m1 = -1e30f, L0 = 0.f, L1 = 0.f;

    uint32_t aqh[4][4], aql[4][4], aqp[4];

    for (int st = 0; st < 16; st++) {
        int p = st & 1;
        if (st + 1 < 16) {
            A_LOAD_STAGE(st + 1, p ^ 1);
            CP_COMMIT();
            CP_WAIT(1);
        } else {
            CP_WAIT(0);
        }
        __syncthreads();

        if (st == 0) {
            // hoist Q fragments (constant across steps)
#pragma unroll
            for (int kt = 0; kt < 4; kt++) {
                int ra = w * 16 + (l & 15);
                int ca = kt * 2 + ((l >> 4) & 1);
                ldsm4(aqh[kt], SWZ(sb + SQ_OFF, ra, ca));
                ldsm4(aql[kt], SWZ(sb + SQ_OFF, ra, ca + 8));
            }
            ldsm4(aqp, sb + SQP_OFF + (w * 16 + (l & 15)) * 48 + ((l >> 4) & 1) * 16);
        }

        uint32_t so = sb + STG_OFF + p * STG_SZ;

        // ---- mask scores: QP @ KP^T ----
        float msk[8][4];
#pragma unroll
        for (int i = 0; i < 8; i++)
#pragma unroll
            for (int j = 0; j < 4; j++) msk[i][j] = 0.f;
#pragma unroll
        for (int g = 0; g < 4; g++) {
            int rk = g * 16 + (l & 7) + ((l >> 4) & 1) * 8;
            uint32_t bkp[4];
            ldsm4(bkp, so + 32768 + rk * 48 + ((l >> 3) & 1) * 16);
            mma16816(msk[g * 2 + 0], aqp, bkp);
            mma16816(msk[g * 2 + 1], aqp, bkp + 2);
        }

        // ---- scores: Q @ K^T (3-product split) ----
        float sc[8][4];
#pragma unroll
        for (int i = 0; i < 8; i++)
#pragma unroll
            for (int j = 0; j < 4; j++) sc[i][j] = 0.f;
#pragma unroll
        for (int kt = 0; kt < 4; kt++) {
#pragma unroll
            for (int g = 0; g < 4; g++) {
                int rk = g * 16 + (l & 7) + ((l >> 4) & 1) * 8;
                int ck = kt * 2 + ((l >> 3) & 1);
                uint32_t bh[4], bl_[4];
                ldsm4(bh,  SWZ(so, rk, ck));
                ldsm4(bl_, SWZ(so, rk, ck + 8));
                mma16816(sc[g * 2 + 0], aqh[kt], bh);
                mma16816(sc[g * 2 + 1], aqh[kt], bh + 2);
                mma16816(sc[g * 2 + 0], aql[kt], bh);
                mma16816(sc[g * 2 + 1], aql[kt], bh + 2);
                mma16816(sc[g * 2 + 0], aqh[kt], bl_);
                mma16816(sc[g * 2 + 1], aqh[kt], bl_ + 2);
            }
        }

        // ---- combine + key-validity mask ----
        int s0 = st << 6;
#pragma unroll
        for (int nt = 0; nt < 8; nt++) {
#pragma unroll
            for (int j = 0; j < 4; j++) {
                int col = nt * 8 + (l & 3) * 2 + (j & 1);
                float s = sc[nt][j] * 0.125f + tanh_fast(msk[nt][j]);
                sc[nt][j] = (s0 + col < LSEQ) ? s : -1e30f;
            }
        }

        // ---- online softmax (rows: j<2 -> r0=l/4, j>=2 -> r0+8) ----
        float mx0 = -1e30f, mx1 = -1e30f;
#pragma unroll
        for (int nt = 0; nt < 8; nt++) {
            mx0 = fmaxf(mx0, fmaxf(sc[nt][0], sc[nt][1]));
            mx1 = fmaxf(mx1, fmaxf(sc[nt][2], sc[nt][3]));
        }
        mx0 = fmaxf(mx0, __shfl_xor_sync(0xffffffffu, mx0, 1));
        mx0 = fmaxf(mx0, __shfl_xor_sync(0xffffffffu, mx0, 2));
        mx1 = fmaxf(mx1, __shfl_xor_sync(0xffffffffu, mx1, 1));
        mx1 = fmaxf(mx1, __shfl_xor_sync(0xffffffffu, mx1, 2));
        float m0n = fmaxf(m0, mx0), m1n = fmaxf(m1, mx1);
        float f0 = __expf(m0 - m0n), f1 = __expf(m1 - m1n);
        m0 = m0n; m1 = m1n;
        float sum0 = 0.f, sum1 = 0.f;
#pragma unroll
        for (int nt = 0; nt < 8; nt++) {
            float p0 = __expf(sc[nt][0] - m0n), p1 = __expf(sc[nt][1] - m0n);
            float p2 = __expf(sc[nt][2] - m1n), p3 = __expf(sc[nt][3] - m1n);
            sc[nt][0] = p0; sc[nt][1] = p1; sc[nt][2] = p2; sc[nt][3] = p3;
            sum0 += p0 + p1; sum1 += p2 + p3;
        }
        sum0 += __shfl_xor_sync(0xffffffffu, sum0, 1);
        sum0 += __shfl_xor_sync(0xffffffffu, sum0, 2);
        sum1 += __shfl_xor_sync(0xffffffffu, sum1, 1);
        sum1 += __shfl_xor_sync(0xffffffffu, sum1, 2);
        L0 = L0 * f0 + sum0;
        L1 = L1 * f1 + sum1;
#pragma unroll
        for (int nt = 0; nt < 8; nt++) {
            o[nt][0] *= f0; o[nt][1] *= f0;
            o[nt][2] *= f1; o[nt][3] *= f1;
        }

        // ---- O += P @ V (3-product split; V via ldmatrix.trans) ----
#pragma unroll
        for (int kt = 0; kt < 4; kt++) {
            uint32_t ph[4], pl[4];
            ph[0] = pack_hi(sc[2 * kt][0],     sc[2 * kt][1]);
            ph[1] = pack_hi(sc[2 * kt][2],     sc[2 * kt][3]);
            ph[2] = pack_hi(sc[2 * kt + 1][0], sc[2 * kt + 1][1]);
            ph[3] = pack_hi(sc[2 * kt + 1][2], sc[2 * kt + 1][3]);
            pl[0] = pack_lo(sc[2 * kt][0],     sc[2 * kt][1]);
            pl[1] = pack_lo(sc[2 * kt][2],     sc[2 * kt][3]);
            pl[2] = pack_lo(sc[2 * kt + 1][0], sc[2 * kt + 1][1]);
            pl[3] = pack_lo(sc[2 * kt + 1][2], sc[2 * kt + 1][3]);
#pragma unroll
            for (int dp = 0; dp < 4; dp++) {
                int rv = kt * 16 + (l & 7) + ((l >> 3) & 1) * 8;
                int cv = dp * 2 + ((l >> 4) & 1);
                uint32_t bvh[4], bvl[4];
                ldsm4t(bvh, SWZ(so + 16384, rv, cv));
                ldsm4t(bvl, SWZ(so + 16384, rv, cv + 8));
                mma16816(o[dp * 2 + 0], ph, bvh);
                mma16816(o[dp * 2 + 1], ph, bvh + 2);
                mma16816(o[dp * 2 + 0], pl, bvh);
                mma16816(o[dp * 2 + 1], pl, bvh + 2);
                mma16816(o[dp * 2 + 0], ph, bvl);
                mma16816(o[dp * 2 + 1], ph, bvl + 2);
            }
        }
        __syncthreads();
    }

    // ---- epilogue: normalize, split, store ctx ----
    float rs0 = 1.f / L0, rs1 = 1.f / L1;
    int r0 = w * 16 + (l >> 2);
    int lq0 = l0 + r0, lq1 = lq0 + 8;
#pragma unroll
    for (int dt = 0; dt < 8; dt++) {
        int col = h * DKH + dt * 8 + (l & 3) * 2;
        if (lq0 < LSEQ) {
            size_t off = (size_t)(b * LSEQ + lq0) * DM + col;
            float v0 = o[dt][0] * rs0, v1 = o[dt][1] * rs0;
            *(uint32_t*)&ch[off] = pack_hi(v0, v1);
            *(uint32_t*)&cl[off] = pack_lo(v0, v1);
        }
        if (lq1 < LSEQ) {
            size_t off = (size_t)(b * LSEQ + lq1) * DM + col;
            float v2 = o[dt][2] * rs1, v3 = o[dt][3] * rs1;
            *(uint32_t*)&ch[off] = pack_hi(v2, v3);
            *(uint32_t*)&cl[off] = pack_lo(v2, v3);
        }
    }
}

// ---------------- LayerNorm (+ optional split out) ----------------
__global__ __launch_bounds__(128)
void ln_kernel(float* __restrict__ out, const float* __restrict__ a,
               const float* __restrict__ y, const float* __restrict__ g,
               const float* __restrict__ bb,
               __nv_bfloat16* __restrict__ oh, __nv_bfloat16* __restrict__ ol)
{
    int row = blockIdx.x, tid = threadIdx.x;
    float4 v = ((const float4*)(a + (long)row * DM))[tid];
    if (y) {
        float4 vy = ((const float4*)(y + (long)row * DM))[tid];
        v.x += vy.x; v.y += vy.y; v.z += vy.z; v.w += vy.w;
    }
    float s  = v.x + v.y + v.z + v.w;
    float sq = v.x * v.x + v.y * v.y + v.z * v.z + v.w * v.w;
#pragma unroll
    for (int o = 16; o > 0; o >>= 1) {
        s  += __shfl_xor_sync(0xffffffffu, s,  o);
        sq += __shfl_xor_sync(0xffffffffu, sq, o);
    }
    __shared__ float shs[4], shq[4];
    int wid = tid >> 5;
    if ((tid & 31) == 0) { shs[wid] = s; shq[wid] = sq; }
    __syncthreads();
    s  = shs[0] + shs[1] + shs[2] + shs[3];
    sq = shq[0] + shq[1] + shq[2] + shq[3];
    float mean = s * (1.f / DM);
    float var  = sq * (1.f / DM) - mean * mean;
    float rstd = rsqrtf(var + 1e-5f);
    float4 gg = ((const float4*)g)[tid];
    float4 bv = ((const float4*)bb)[tid];
    float4 o4;
    o4.x = (v.x - mean) * rstd * gg.x + bv.x;
    o4.y = (v.y - mean) * rstd * gg.y + bv.y;
    o4.z = (v.z - mean) * rstd * gg.z + bv.z;
    o4.w = (v.w - mean) * rstd * gg.w + bv.w;
    ((float4*)(out + (long)row * DM))[tid] = o4;
    if (oh) {
        ((uint32_t*)(oh + (long)row * DM))[tid * 2]     = pack_hi(o4.x, o4.y);
        ((uint32_t*)(oh + (long)row * DM))[tid * 2 + 1] = pack_hi(o4.z, o4.w);
        ((uint32_t*)(ol + (long)row * DM))[tid * 2]     = pack_lo(o4.x, o4.y);
        ((uint32_t*)(ol + (long)row * DM))[tid * 2 + 1] = pack_lo(o4.z, o4.w);
    }
}

// ---------------- final FC on last token ----------------
__global__ __launch_bounds__(64)
void fc_kernel(const float* __restrict__ hin, const float* __restrict__ w,
               const float* __restrict__ b, float* __restrict__ out)
{
    __shared__ float sh[512];
    int tid = threadIdx.x;
    int bb  = blockIdx.x;
    const float* row = hin + ((long)bb * LSEQ + (LSEQ - 1)) * DM;
    for (int i = tid; i < 512; i += 64) sh[i] = row[i];
    __syncthreads();
    if (tid < 50) {
        float a = b[tid];
#pragma unroll 8
        for (int d = 0; d < 512; d++) a += sh[d] * w[d * 50 + tid];
        out[bb * 50 + tid] = a;
    }
}

// ---------------- launch ----------------
extern "C" void kernel_launch(void* const* d_in, const int* in_sizes, int n_in,
                              void* d_out, int out_size)
{
    const float* x     = (const float*)d_in[0];
    const float* emb_w = (const float*)d_in[1];
    const float* emb_b = (const float*)d_in[2];
    const float* pe    = (const float*)d_in[3];
    const float* Wq    = (const float*)d_in[4];
    const float* bq    = (const float*)d_in[5];
    const float* Wk    = (const float*)d_in[6];
    const float* bk    = (const float*)d_in[7];
    const float* Wv    = (const float*)d_in[8];
    const float* bv    = (const float*)d_in[9];
    const float* Wo    = (const float*)d_in[10];
    const float* bo    = (const float*)d_in[11];
    const float* W1    = (const float*)d_in[12];
    const float* b1    = (const float*)d_in[13];
    const float* W2    = (const float*)d_in[14];
    const float* b2    = (const float*)d_in[15];
    const float* g1    = (const float*)d_in[16];
    const float* be1   = (const float*)d_in[17];
    const float* g2    = (const float*)d_in[18];
    const float* be2   = (const float*)d_in[19];
    const float* lm_qw = (const float*)d_in[20];
    const float* lm_qb = (const float*)d_in[21];
    const float* lm_kw = (const float*)d_in[22];
    const float* lm_kb = (const float*)d_in[23];
    const float* gn    = (const float*)d_in[24];
    const float* bn    = (const float*)d_in[25];
    const float* fc_w  = (const float*)d_in[26];
    const float* fc_b  = (const float*)d_in[27];
    float* out = (float*)d_out;

    float *h, *t1, *t2;
    cudaGetSymbolAddress((void**)&h,  g_h);
    cudaGetSymbolAddress((void**)&t1, g_t1);
    cudaGetSymbolAddress((void**)&t2, g_t2);

    __nv_bfloat16 *wqh, *wql, *wkh, *wkl, *wvh, *wvl, *woh, *wol;
    __nv_bfloat16 *w1h, *w1l, *w2h, *w2l, *ah, *al, *ffh, *ffl;
    __nv_bfloat16 *qh, *ql, *kh, *kl, *vh, *vl, *qpb, *kpb;
    cudaGetSymbolAddress((void**)&wqh, g_wqh);
    cudaGetSymbolAddress((void**)&wql, g_wql);
    cudaGetSymbolAddress((void**)&wkh, g_wkh);
    cudaGetSymbolAddress((void**)&wkl, g_wkl);
    cudaGetSymbolAddress((void**)&wvh, g_wvh);
    cudaGetSymbolAddress((void**)&wvl, g_wvl);
    cudaGetSymbolAddress((void**)&woh, g_woh);
    cudaGetSymbolAddress((void**)&wol, g_wol);
    cudaGetSymbolAddress((void**)&w1h, g_w1h);
    cudaGetSymbolAddress((void**)&w1l, g_w1l);
    cudaGetSymbolAddress((void**)&w2h, g_w2h);
    cudaGetSymbolAddress((void**)&w2l, g_w2l);
    cudaGetSymbolAddress((void**)&ah,  g_ah);
    cudaGetSymbolAddress((void**)&al,  g_al);
    cudaGetSymbolAddress((void**)&ffh, g_ffh);
    cudaGetSymbolAddress((void**)&ffl, g_ffl);
    cudaGetSymbolAddress((void**)&qh,  g_qh);
    cudaGetSymbolAddress((void**)&ql,  g_ql);
    cudaGetSymbolAddress((void**)&kh,  g_kh);
    cudaGetSymbolAddress((void**)&kl,  g_kl);
    cudaGetSymbolAddress((void**)&vh,  g_vh);
    cudaGetSymbolAddress((void**)&vl,  g_vl);
    cudaGetSymbolAddress((void**)&qpb, g_qp);
    cudaGetSymbolAddress((void**)&kpb, g_kp);

    cudaFuncSetAttribute(attn_kernel, cudaFuncAttributeMaxDynamicSharedMemorySize, ATT_SMEM);
    cudaFuncSetAttribute(mma_gemm,    cudaFuncAttributeMaxDynamicSharedMemorySize, MMA_SMEM);

    wsplit_all<<<NL * 3072, 256>>>(Wq, Wk, Wv, Wo, W1, W2,
                                   wqh, wql, wkh, wkl, wvh, wvl, woh, wol,
                                   w1h, w1l, w2h, w2l);
    embed_kernel<<<BL, 128>>>(x, emb_w, emb_b, pe, h, ah, al);

    const int MT = MPAD / 128;
    dim3 gq(DM / 128, MT);
    dim3 gf1(DFF / 128, MT);

    for (int i = 0; i < NL; i++) {
        long o512 = (long)i * DM * DM;
        long offf = (long)i * DM * DFF;

        // launch idx (layer 0): 2=Q, 3=K, 4=lmq, 5=V (ncu -s5 -c1 -> V mma_gemm)
        mma_gemm<<<gq, 256, MMA_SMEM>>>(ah, al, wqh + o512, wql + o512, bq + i * DM,
                                        (float*)0, qh, ql, DM, DM, 4);
        mma_gemm<<<gq, 256, MMA_SMEM>>>(ah, al, wkh + o512, wkl + o512, bk + i * DM,
                                        (float*)0, kh, kl, DM, DM, 4);
        lmproj_kernel<<<BL, 128>>>(qh, lm_qw, lm_qb, qpb);
        mma_gemm<<<gq, 256, MMA_SMEM>>>(ah, al, wvh + o512, wvl + o512, bv + i * DM,
                                        (float*)0, vh, vl, DM, DM, 4);
        lmproj_kernel<<<BL, 128>>>(kh, lm_kw, lm_kb, kpb);

        attn_kernel<<<NB * NH * 16, 128, ATT_SMEM>>>(qh, ql, kh, kl, vh, vl, qpb, kpb, ah, al);

        mma_gemm<<<gq, 256, MMA_SMEM>>>(ah, al, woh + o512, wol + o512, bo + i * DM, t1,
                                        (__nv_bfloat16*)0, (__nv_bfloat16*)0, DM, DM, 2);
        ln_kernel<<<BL, 128>>>(h, h, t1, g1 + i * DM, be1 + i * DM, ah, al);

        mma_gemm<<<gf1, 256, MMA_SMEM>>>(ah, al, w1h + offf, w1l + offf, b1 + i * DFF,
                                         (float*)0, ffh, ffl, DFF, DM, 5);
        mma_gemm<<<gq, 256, MMA_SMEM>>>(ffh, ffl, w2h + offf, w2l + offf, b2 + i * DM, t2,
                                        (__nv_bfloat16*)0, (__nv_bfloat16*)0, DM, DFF, 2);

        ln_kernel<<<BL, 128>>>(t1, h, t2, g2 + i * DM, be2 + i * DM,
                               (__nv_bfloat16*)0, (__nv_bfloat16*)0);
        ln_kernel<<<BL, 128>>>(h, t1, t2, g2 + i * DM, be2 + i * DM, ah, al);
    }

    ln_kernel<<<BL, 128>>>(t1, h, (const float*)nullptr, gn, bn,
                           (__nv_bfloat16*)0, (__nv_bfloat16*)0);
    fc_kernel<<<NB, 64>>>(t1, fc_w, fc_b, out);
}

// round 11
// speedup vs baseline: 3.1480x; 1.5176x over previous
#include <cuda_runtime.h>
#include <cuda_bf16.h>
#include <math.h>
#include <stdint.h>

#define BL    8000
#define MPAD  8064
#define DM    512
#define DFF   2048
#define NL    4
#define LSEQ  1000
#define NB    8
#define NH    8
#define DKH   64
#define PP    16

// ---------------- scratch (device globals; no allocation allowed) ----------------
__device__ float g_h  [BL * DM];
__device__ float g_t1 [BL * DM];
__device__ float g_t2 [BL * DM];

// bf16 split weight buffers (transposed to [N,K])
__device__ __nv_bfloat16 g_wqh[NL * DM * DM];
__device__ __nv_bfloat16 g_wql[NL * DM * DM];
__device__ __nv_bfloat16 g_wkh[NL * DM * DM];
__device__ __nv_bfloat16 g_wkl[NL * DM * DM];
__device__ __nv_bfloat16 g_wvh[NL * DM * DM];
__device__ __nv_bfloat16 g_wvl[NL * DM * DM];
__device__ __nv_bfloat16 g_woh[NL * DM * DM];
__device__ __nv_bfloat16 g_wol[NL * DM * DM];
__device__ __nv_bfloat16 g_w1h[NL * DM * DFF];
__device__ __nv_bfloat16 g_w1l[NL * DM * DFF];
__device__ __nv_bfloat16 g_w2h[NL * DFF * DM];
__device__ __nv_bfloat16 g_w2l[NL * DFF * DM];
// bf16 split activation buffers
__device__ __nv_bfloat16 g_ah [MPAD * DM];
__device__ __nv_bfloat16 g_al [MPAD * DM];
__device__ __nv_bfloat16 g_ffh[MPAD * DFF];
__device__ __nv_bfloat16 g_ffl[MPAD * DFF];
// split qkv
__device__ __nv_bfloat16 g_qh [MPAD * DM];
__device__ __nv_bfloat16 g_ql [MPAD * DM];
__device__ __nv_bfloat16 g_kh [MPAD * DM];
__device__ __nv_bfloat16 g_kl [MPAD * DM];
__device__ __nv_bfloat16 g_vh [MPAD * DM];
__device__ __nv_bfloat16 g_vl [MPAD * DM];
// learned-mask projections (bf16)
__device__ __nv_bfloat16 g_qp [BL * NH * PP];
__device__ __nv_bfloat16 g_kp [BL * NH * PP];

// ================= PTX helpers (baseline ISA only) =================
__device__ __forceinline__ uint32_t smem_u32(const void* p) {
    uint32_t a;
    asm("{ .reg .u64 t; cvta.to.shared.u64 t, %1; cvt.u32.u64 %0, t; }" : "=r"(a) : "l"(p));
    return a;
}
__device__ __forceinline__ void cpa16(uint32_t s, const void* g) {
    asm volatile("cp.async.cg.shared.global [%0], [%1], 16;" :: "r"(s), "l"(g));
}
__device__ __forceinline__ void cpa16z(uint32_t s, const void* g, int sz) {
    asm volatile("cp.async.cg.shared.global [%0], [%1], 16, %2;" :: "r"(s), "l"(g), "r"(sz));
}
#define CP_COMMIT() asm volatile("cp.async.commit_group;" ::: "memory")
#define CP_WAIT(n)  asm volatile("cp.async.wait_group %0;" :: "n"(n) : "memory")

__device__ __forceinline__ void ldsm4(uint32_t* r, uint32_t addr) {
    asm volatile("ldmatrix.sync.aligned.m8n8.x4.shared.b16 {%0,%1,%2,%3}, [%4];"
                 : "=r"(r[0]), "=r"(r[1]), "=r"(r[2]), "=r"(r[3]) : "r"(addr));
}
__device__ __forceinline__ void ldsm4t(uint32_t* r, uint32_t addr) {
    asm volatile("ldmatrix.sync.aligned.m8n8.x4.trans.shared.b16 {%0,%1,%2,%3}, [%4];"
                 : "=r"(r[0]), "=r"(r[1]), "=r"(r[2]), "=r"(r[3]) : "r"(addr));
}
__device__ __forceinline__ void mma16816(float* d, const uint32_t* a, const uint32_t* b) {
    asm volatile("mma.sync.aligned.m16n8k16.row.col.f32.bf16.bf16.f32 "
                 "{%0,%1,%2,%3}, {%4,%5,%6,%7}, {%8,%9}, {%0,%1,%2,%3};"
                 : "+f"(d[0]), "+f"(d[1]), "+f"(d[2]), "+f"(d[3])
                 : "r"(a[0]), "r"(a[1]), "r"(a[2]), "r"(a[3]), "r"(b[0]), "r"(b[1]));
}
__device__ __forceinline__ float tanh_fast(float x) {
    float r;
    asm("tanh.approx.f32 %0, %1;" : "=f"(r) : "f"(x));
    return r;
}
__device__ __forceinline__ void split_bf16(float v, __nv_bfloat16& hi, __nv_bfloat16& lo) {
    hi = __float2bfloat16(v);
    lo = __float2bfloat16(v - __bfloat162float(hi));
}
__device__ __forceinline__ uint32_t pack_hi(float a, float b) {
    __nv_bfloat162 h; h.x = __float2bfloat16(a); h.y = __float2bfloat16(b);
    return *(uint32_t*)&h;
}
__device__ __forceinline__ uint32_t pack_lo(float a, float b) {
    __nv_bfloat16 ha = __float2bfloat16(a), hb = __float2bfloat16(b);
    __nv_bfloat162 h;
    h.x = __float2bfloat16(a - __bfloat162float(ha));
    h.y = __float2bfloat16(b - __bfloat162float(hb));
    return *(uint32_t*)&h;
}

// ---------------- all-weights transpose + split (single launch) ----------------
__global__ __launch_bounds__(256)
void wsplit_all(const float* __restrict__ Wq, const float* __restrict__ Wk,
                const float* __restrict__ Wv, const float* __restrict__ Wo,
                const float* __restrict__ W1, const float* __restrict__ W2,
                __nv_bfloat16* qh, __nv_bfloat16* ql, __nv_bfloat16* kh, __nv_bfloat16* kl,
                __nv_bfloat16* vh, __nv_bfloat16* vl, __nv_bfloat16* oh_, __nv_bfloat16* ol_,
                __nv_bfloat16* f1h, __nv_bfloat16* f1l, __nv_bfloat16* f2h, __nv_bfloat16* f2l)
{
    int t = blockIdx.x;
    int layer = t / 3072, r = t % 3072;
    const float* in; __nv_bfloat16 *oh, *ol;
    int K, N, nx, ky;
    if (r < 1024) {
        int type = r >> 8, tt = r & 255;
        nx = tt & 15; ky = tt >> 4; K = DM; N = DM;
        long off = (long)layer * DM * DM;
        if (type == 0)      { in = Wq + off; oh = qh + off;  ol = ql + off;  }
        else if (type == 1) { in = Wk + off; oh = kh + off;  ol = kl + off;  }
        else if (type == 2) { in = Wv + off; oh = vh + off;  ol = vl + off;  }
        else                { in = Wo + off; oh = oh_ + off; ol = ol_ + off; }
    } else if (r < 2048) {
        int tt = r - 1024;
        nx = tt & 63; ky = tt >> 6; K = DM; N = DFF;
        long off = (long)layer * DM * DFF;
        in = W1 + off; oh = f1h + off; ol = f1l + off;
    } else {
        int tt = r - 2048;
        nx = tt & 15; ky = tt >> 4; K = DFF; N = DM;
        long off = (long)layer * DFF * DM;
        in = W2 + off; oh = f2h + off; ol = f2l + off;
    }

    __shared__ float s[32][33];
    int n0 = nx * 32, k0 = ky * 32;
    int tx = threadIdx.x & 31, ty = threadIdx.x >> 5;
#pragma unroll
    for (int rr = 0; rr < 32; rr += 8)
        s[rr + ty][tx] = in[(size_t)(k0 + rr + ty) * N + n0 + tx];
    __syncthreads();
#pragma unroll
    for (int rr = 0; rr < 32; rr += 8) {
        float v = s[tx][rr + ty];
        __nv_bfloat16 hi, lo; split_bf16(v, hi, lo);
        size_t o = (size_t)(n0 + rr + ty) * K + k0 + tx;
        oh[o] = hi; ol[o] = lo;
    }
}

// ---------------- HMMA bf16-split GEMM (XOR-swizzled smem, 3-stage ring) ----------------
// Stage tile: A[128 rows x 128B] (chunks 0-3 = hi k0..31, 4-7 = lo), B same.
// mode bits: 1=relu, 2=write fp32 C, 4=write split Ch/Cl.
#define GST       16384
#define GSTAGE    32768
#define MMA_SMEM  (3 * GSTAGE)

__global__ __launch_bounds__(256, 2)
void mma_gemm(const __nv_bfloat16* __restrict__ Ah, const __nv_bfloat16* __restrict__ Al,
              const __nv_bfloat16* __restrict__ Bh, const __nv_bfloat16* __restrict__ Bl,
              const float* __restrict__ bias, float* __restrict__ C,
              __nv_bfloat16* __restrict__ Ch, __nv_bfloat16* __restrict__ Cl,
              int N, int K, int mode)
{
    extern __shared__ char smraw[];
    uint32_t sb = smem_u32(smraw);

    int tid = threadIdx.x;
    int l = tid & 31, w = tid >> 5;
    int wm = w >> 1, wn = w & 1;
    int bn = blockIdx.x << 7, bm = blockIdx.y << 7;
    size_t rowb = (size_t)K * 2;

    const char* gAh = (const char*)Ah + (size_t)bm * rowb;
    const char* gAl = (const char*)Al + (size_t)bm * rowb;
    const char* gBh = (const char*)Bh + (size_t)bn * rowb;
    const char* gBl = (const char*)Bl + (size_t)bn * rowb;

    float d[2][8][4];
#pragma unroll
    for (int i = 0; i < 2; i++)
#pragma unroll
        for (int j = 0; j < 8; j++)
#pragma unroll
            for (int t = 0; t < 4; t++) d[i][j][t] = 0.f;

    const int S = K >> 5;

#define G_LOAD_STAGE(stg, buf) do { \
    _Pragma("unroll") \
    for (int i = 0; i < 8; i++) { \
        int id = i * 256 + tid; \
        int ab = id >> 10, rem = id & 1023; \
        int row = rem >> 3, c = rem & 7; \
        const char* gh = ab ? gBh : gAh; \
        const char* gl = ab ? gBl : gAl; \
        const char* src = (c < 4 ? gh : gl) + (size_t)row * rowb + (size_t)(stg) * 64 + (c & 3) * 16; \
        uint32_t dst = sb + (buf) * GSTAGE + ab * GST + row * 128 + ((c ^ (row & 7)) << 4); \
        cpa16(dst, src); \
    } \
} while (0)

    G_LOAD_STAGE(0, 0);
    CP_COMMIT();
    if (S > 1) { G_LOAD_STAGE(1, 1); }
    CP_COMMIT();

    int p = 0;
    for (int s = 0; s < S; s++) {
        if (s + 1 < S) CP_WAIT(1); else CP_WAIT(0);
        __syncthreads();

        // issue load for s+2 into the buffer freed by compute(s-1)
        if (s + 2 < S) {
            int nb = p + 2; if (nb >= 3) nb -= 3;
            G_LOAD_STAGE(s + 2, nb);
        }
        CP_COMMIT();

        uint32_t bufo = sb + p * GSTAGE;
#pragma unroll
        for (int kk = 0; kk < 2; kk++) {
            uint32_t ahf[2][4], alf[2][4];
#pragma unroll
            for (int mt = 0; mt < 2; mt++) {
                int ra = wm * 32 + mt * 16 + (l & 15);
                int ca = kk * 2 + ((l >> 4) & 1);
                ldsm4(ahf[mt], bufo + ra * 128 + ((ca ^ (ra & 7)) << 4));
                ldsm4(alf[mt], bufo + ra * 128 + (((ca + 4) ^ (ra & 7)) << 4));
            }
            // double-buffered B fragments: prefetch g+1 while mma on g
            uint32_t bh[2][4], blo[2][4];
            {
                int rb = wn * 64 + (l & 7) + ((l >> 4) & 1) * 8;
                int cb = kk * 2 + ((l >> 3) & 1);
                ldsm4(bh[0],  bufo + GST + rb * 128 + ((cb ^ (rb & 7)) << 4));
                ldsm4(blo[0], bufo + GST + rb * 128 + (((cb + 4) ^ (rb & 7)) << 4));
            }
#pragma unroll
            for (int g = 0; g < 4; g++) {
                int cur = g & 1, nxt = cur ^ 1;
                if (g < 3) {
                    int rb = wn * 64 + (g + 1) * 16 + (l & 7) + ((l >> 4) & 1) * 8;
                    int cb = kk * 2 + ((l >> 3) & 1);
                    ldsm4(bh[nxt],  bufo + GST + rb * 128 + ((cb ^ (rb & 7)) << 4));
                    ldsm4(blo[nxt], bufo + GST + rb * 128 + (((cb + 4) ^ (rb & 7)) << 4));
                }
#pragma unroll
                for (int mt = 0; mt < 2; mt++) {
                    mma16816(d[mt][g * 2 + 0], ahf[mt], bh[cur]);
                    mma16816(d[mt][g * 2 + 1], ahf[mt], bh[cur] + 2);
                    mma16816(d[mt][g * 2 + 0], alf[mt], bh[cur]);
                    mma16816(d[mt][g * 2 + 1], alf[mt], bh[cur] + 2);
                    mma16816(d[mt][g * 2 + 0], ahf[mt], blo[cur]);
                    mma16816(d[mt][g * 2 + 1], ahf[mt], blo[cur] + 2);
                }
            }
        }
        if (++p == 3) p = 0;
    }

    // ---- epilogue ----
    bool dorelu = (mode & 1), dof32 = (mode & 2), dosplit = (mode & 4);
#pragma unroll
    for (int mt = 0; mt < 2; mt++) {
        int r0 = bm + wm * 32 + mt * 16 + (l >> 2);
        int r1 = r0 + 8;
#pragma unroll
        for (int nt = 0; nt < 8; nt++) {
            int c = bn + wn * 64 + nt * 8 + (l & 3) * 2;
            float b0 = bias[c], b1 = bias[c + 1];
            float v0 = d[mt][nt][0] + b0, v1 = d[mt][nt][1] + b1;
            float v2 = d[mt][nt][2] + b0, v3 = d[mt][nt][3] + b1;
            if (dorelu) {
                v0 = fmaxf(v0, 0.f); v1 = fmaxf(v1, 0.f);
                v2 = fmaxf(v2, 0.f); v3 = fmaxf(v3, 0.f);
            }
            if (dof32) {
                if (r0 < BL) { float2 t = {v0, v1}; *(float2*)&C[(size_t)r0 * N + c] = t; }
                if (r1 < BL) { float2 t = {v2, v3}; *(float2*)&C[(size_t)r1 * N + c] = t; }
            }
            if (dosplit) {
                if (r0 < BL) {
                    *(uint32_t*)&Ch[(size_t)r0 * N + c] = pack_hi(v0, v1);
                    *(uint32_t*)&Cl[(size_t)r0 * N + c] = pack_lo(v0, v1);
                }
                if (r1 < BL) {
                    *(uint32_t*)&Ch[(size_t)r1 * N + c] = pack_hi(v2, v3);
                    *(uint32_t*)&Cl[(size_t)r1 * N + c] = pack_lo(v2, v3);
                }
            }
        }
    }
}

// ---------------- embed: h = x @ emb_w + emb_b + pe[l], + split out ----------------
__global__ __launch_bounds__(128)
void embed_kernel(const float* __restrict__ x, const float* __restrict__ ew,
                  const float* __restrict__ eb, const float* __restrict__ pe,
                  float* __restrict__ h, __nv_bfloat16* __restrict__ ah,
                  __nv_bfloat16* __restrict__ al)
{
    __shared__ float sx[7];
    int row = blockIdx.x;
    int l   = row % LSEQ;
    int tid = threadIdx.x;
    if (tid < 7) sx[tid] = x[row * 7 + tid];
    __syncthreads();
    for (int d = tid; d < DM; d += 128) {
        float a = eb[d] + pe[l * DM + d];
#pragma unroll
        for (int f = 0; f < 7; f++) a += sx[f] * ew[f * DM + d];
        h[(long)row * DM + d] = a;
        __nv_bfloat16 hi, lo; split_bf16(a, hi, lo);
        ah[(long)row * DM + d] = hi;
        al[(long)row * DM + d] = lo;
    }
}

// ---------------- learned-mask projection (bf16 in / bf16 out) ----------------
__global__ __launch_bounds__(128)
void lmproj_kernel(const __nv_bfloat16* __restrict__ q, const float* __restrict__ w,
                   const float* __restrict__ b, __nv_bfloat16* __restrict__ o)
{
    __shared__ float sw[64 * 16];
    __shared__ float sq[8 * 64];
    int tid = threadIdx.x;
    int r0  = blockIdx.x * 8;
    for (int i = tid; i < 1024; i += 128) sw[i] = w[i];
    for (int i = tid; i < 512;  i += 128) sq[i] = __bfloat162float(q[(long)r0 * 64 + i]);
    __syncthreads();
    int rr = tid >> 4, p = tid & 15;
    float a = b[p];
#pragma unroll
    for (int d = 0; d < 64; d++) a += sq[rr * 64 + d] * sw[d * 16 + p];
    o[(long)(r0 + rr) * 16 + p] = __float2bfloat16(a);
}

// ---------------- tensor-core fused attention ----------------
#define SQ_OFF   0
#define SQP_OFF  16384
#define STG_OFF  19456
#define STG_SZ   35840          // K 16384 + V 16384 + KP 3072
#define ATT_SMEM (19456 + 2 * STG_SZ)   // 91136

#define SWZ(base, row, c) \
    ((base) + (row) * 256 + (((c) < 8) ? (((c) ^ ((row) & 7)) << 4) \
                                       : (128 + ((((c) - 8) ^ ((row) & 7)) << 4))))

__global__ __launch_bounds__(128)
void attn_kernel(const __nv_bfloat16* __restrict__ qh, const __nv_bfloat16* __restrict__ ql,
                 const __nv_bfloat16* __restrict__ kh, const __nv_bfloat16* __restrict__ kl,
                 const __nv_bfloat16* __restrict__ vh, const __nv_bfloat16* __restrict__ vl,
                 const __nv_bfloat16* __restrict__ qp, const __nv_bfloat16* __restrict__ kp,
                 __nv_bfloat16* __restrict__ ch, __nv_bfloat16* __restrict__ cl)
{
    extern __shared__ char smraw[];
    uint32_t sb = smem_u32(smraw);
    int tid = threadIdx.x;
    int l = tid & 31, w = tid >> 5;
    int bid = blockIdx.x;
    int qt = bid & 15;
    int h  = (bid >> 4) & 7;
    int b  = bid >> 7;
    int l0 = qt << 6;

    {
#pragma unroll
        for (int i = 0; i < 8; i++) {
            int id = i * 128 + tid;
            int row = id >> 4, c = id & 15;
            int lq = l0 + row;
            const __nv_bfloat16* base = (c < 8) ? qh : ql;
            const __nv_bfloat16* src = base + ((size_t)(b * LSEQ + (lq < LSEQ ? lq : 0))) * DM + h * DKH + (c & 7) * 8;
            cpa16z(SWZ(sb + SQ_OFF, row, c), src, lq < LSEQ ? 16 : 0);
        }
        int row = tid >> 1, cc = tid & 1;
        int lq = l0 + row;
        const __nv_bfloat16* src = qp + ((size_t)((b * LSEQ + (lq < LSEQ ? lq : 0)) * NH + h)) * PP + cc * 8;
        cpa16z(sb + SQP_OFF + row * 48 + cc * 16, src, lq < LSEQ ? 16 : 0);
    }

#define A_LOAD_STAGE(st, buf) do { \
    uint32_t so = sb + STG_OFF + (buf) * STG_SZ; \
    _Pragma("unroll") \
    for (int i = 0; i < 8; i++) { \
        int id = i * 128 + tid; \
        int row = id >> 4, c = id & 15; \
        int s = (st) * 64 + row; \
        int ok = (s < LSEQ) ? 16 : 0; \
        size_t go = ((size_t)(b * LSEQ + (s < LSEQ ? s : 0))) * DM + h * DKH + (c & 7) * 8; \
        cpa16z(SWZ(so, row, c),         ((c < 8) ? kh : kl) + go, ok); \
        cpa16z(SWZ(so + 16384, row, c), ((c < 8) ? vh : vl) + go, ok); \
    } \
    { \
        int row = tid >> 1, cc = tid & 1; \
        int s = (st) * 64 + row; \
        const __nv_bfloat16* src = kp + ((size_t)((b * LSEQ + (s < LSEQ ? s : 0)) * NH + h)) * PP + cc * 8; \
        cpa16z(so + 32768 + row * 48 + cc * 16, src, s < LSEQ ? 16 : 0); \
    } \
} while (0)

    A_LOAD_STAGE(0, 0);
    CP_COMMIT();

    float o[8][4];
#pragma unroll
    for (int i = 0; i < 8; i++)
#pragma unroll
        for (int j = 0; j < 4; j++) o[i][j] = 0.f;
    float m0 = -1e30f, m1 = -1e30f, L0 = 0.f, L1 = 0.f;

    uint32_t aqh[4][4], aql[4][4], aqp[4];

    for (int st = 0; st < 16; st++) {
        int p = st & 1;
        if (st + 1 < 16) {
            A_LOAD_STAGE(st + 1, p ^ 1);
            CP_COMMIT();
            CP_WAIT(1);
        } else {
            CP_WAIT(0);
        }
        __syncthreads();

        if (st == 0) {
#pragma unroll
            for (int kt = 0; kt < 4; kt++) {
                int ra = w * 16 + (l & 15);
                int ca = kt * 2 + ((l >> 4) & 1);
                ldsm4(aqh[kt], SWZ(sb + SQ_OFF, ra, ca));
                ldsm4(aql[kt], SWZ(sb + SQ_OFF, ra, ca + 8));
            }
            ldsm4(aqp, sb + SQP_OFF + (w * 16 + (l & 15)) * 48 + ((l >> 4) & 1) * 16);
        }

        uint32_t so = sb + STG_OFF + p * STG_SZ;

        float msk[8][4];
#pragma unroll
        for (int i = 0; i < 8; i++)
#pragma unroll
            for (int j = 0; j < 4; j++) msk[i][j] = 0.f;
#pragma unroll
        for (int g = 0; g < 4; g++) {
            int rk = g * 16 + (l & 7) + ((l >> 4) & 1) * 8;
            uint32_t bkp[4];
            ldsm4(bkp, so + 32768 + rk * 48 + ((l >> 3) & 1) * 16);
            mma16816(msk[g * 2 + 0], aqp, bkp);
            mma16816(msk[g * 2 + 1], aqp, bkp + 2);
        }

        float sc[8][4];
#pragma unroll
        for (int i = 0; i < 8; i++)
#pragma unroll
            for (int j = 0; j < 4; j++) sc[i][j] = 0.f;
#pragma unroll
        for (int kt = 0; kt < 4; kt++) {
#pragma unroll
            for (int g = 0; g < 4; g++) {
                int rk = g * 16 + (l & 7) + ((l >> 4) & 1) * 8;
                int ck = kt * 2 + ((l >> 3) & 1);
                uint32_t bh[4], bl_[4];
                ldsm4(bh,  SWZ(so, rk, ck));
                ldsm4(bl_, SWZ(so, rk, ck + 8));
                mma16816(sc[g * 2 + 0], aqh[kt], bh);
                mma16816(sc[g * 2 + 1], aqh[kt], bh + 2);
                mma16816(sc[g * 2 + 0], aql[kt], bh);
                mma16816(sc[g * 2 + 1], aql[kt], bh + 2);
                mma16816(sc[g * 2 + 0], aqh[kt], bl_);
                mma16816(sc[g * 2 + 1], aqh[kt], bl_ + 2);
            }
        }

        int s0 = st << 6;
#pragma unroll
        for (int nt = 0; nt < 8; nt++) {
#pragma unroll
            for (int j = 0; j < 4; j++) {
                int col = nt * 8 + (l & 3) * 2 + (j & 1);
                float s = sc[nt][j] * 0.125f + tanh_fast(msk[nt][j]);
                sc[nt][j] = (s0 + col < LSEQ) ? s : -1e30f;
            }
        }

        float mx0 = -1e30f, mx1 = -1e30f;
#pragma unroll
        for (int nt = 0; nt < 8; nt++) {
            mx0 = fmaxf(mx0, fmaxf(sc[nt][0], sc[nt][1]));
            mx1 = fmaxf(mx1, fmaxf(sc[nt][2], sc[nt][3]));
        }
        mx0 = fmaxf(mx0, __shfl_xor_sync(0xffffffffu, mx0, 1));
        mx0 = fmaxf(mx0, __shfl_xor_sync(0xffffffffu, mx0, 2));
        mx1 = fmaxf(mx1, __shfl_xor_sync(0xffffffffu, mx1, 1));
        mx1 = fmaxf(mx1, __shfl_xor_sync(0xffffffffu, mx1, 2));
        float m0n = fmaxf(m0, mx0), m1n = fmaxf(m1, mx1);
        float f0 = __expf(m0 - m0n), f1 = __expf(m1 - m1n);
        m0 = m0n; m1 = m1n;
        float sum0 = 0.f, sum1 = 0.f;
#pragma unroll
        for (int nt = 0; nt < 8; nt++) {
            float p0 = __expf(sc[nt][0] - m0n), p1 = __expf(sc[nt][1] - m0n);
            float p2 = __expf(sc[nt][2] - m1n), p3 = __expf(sc[nt][3] - m1n);
            sc[nt][0] = p0; sc[nt][1] = p1; sc[nt][2] = p2; sc[nt][3] = p3;
            sum0 += p0 + p1; sum1 += p2 + p3;
        }
        sum0 += __shfl_xor_sync(0xffffffffu, sum0, 1);
        sum0 += __shfl_xor_sync(0xffffffffu, sum0, 2);
        sum1 += __shfl_xor_sync(0xffffffffu, sum1, 1);
        sum1 += __shfl_xor_sync(0xffffffffu, sum1, 2);
        L0 = L0 * f0 + sum0;
        L1 = L1 * f1 + sum1;
#pragma unroll
        for (int nt = 0; nt < 8; nt++) {
            o[nt][0] *= f0; o[nt][1] *= f0;
            o[nt][2] *= f1; o[nt][3] *= f1;
        }

#pragma unroll
        for (int kt = 0; kt < 4; kt++) {
            uint32_t ph[4], pl[4];
            ph[0] = pack_hi(sc[2 * kt][0],     sc[2 * kt][1]);
            ph[1] = pack_hi(sc[2 * kt][2],     sc[2 * kt][3]);
            ph[2] = pack_hi(sc[2 * kt + 1][0], sc[2 * kt + 1][1]);
            ph[3] = pack_hi(sc[2 * kt + 1][2], sc[2 * kt + 1][3]);
            pl[0] = pack_lo(sc[2 * kt][0],     sc[2 * kt][1]);
            pl[1] = pack_lo(sc[2 * kt][2],     sc[2 * kt][3]);
            pl[2] = pack_lo(sc[2 * kt + 1][0], sc[2 * kt + 1][1]);
            pl[3] = pack_lo(sc[2 * kt + 1][2], sc[2 * kt + 1][3]);
#pragma unroll
            for (int dp = 0; dp < 4; dp++) {
                int rv = kt * 16 + (l & 7) + ((l >> 3) & 1) * 8;
                int cv = dp * 2 + ((l >> 4) & 1);
                uint32_t bvh[4], bvl[4];
                ldsm4t(bvh, SWZ(so + 16384, rv, cv));
                ldsm4t(bvl, SWZ(so + 16384, rv, cv + 8));
                mma16816(o[dp * 2 + 0], ph, bvh);
                mma16816(o[dp * 2 + 1], ph, bvh + 2);
                mma16816(o[dp * 2 + 0], pl, bvh);
                mma16816(o[dp * 2 + 1], pl, bvh + 2);
                mma16816(o[dp * 2 + 0], ph, bvl);
                mma16816(o[dp * 2 + 1], ph, bvl + 2);
            }
        }
        __syncthreads();
    }

    float rs0 = 1.f / L0, rs1 = 1.f / L1;
    int r0 = w * 16 + (l >> 2);
    int lq0 = l0 + r0, lq1 = lq0 + 8;
#pragma unroll
    for (int dt = 0; dt < 8; dt++) {
        int col = h * DKH + dt * 8 + (l & 3) * 2;
        if (lq0 < LSEQ) {
            size_t off = (size_t)(b * LSEQ + lq0) * DM + col;
            float v0 = o[dt][0] * rs0, v1 = o[dt][1] * rs0;
            *(uint32_t*)&ch[off] = pack_hi(v0, v1);
            *(uint32_t*)&cl[off] = pack_lo(v0, v1);
        }
        if (lq1 < LSEQ) {
            size_t off = (size_t)(b * LSEQ + lq1) * DM + col;
            float v2 = o[dt][2] * rs1, v3 = o[dt][3] * rs1;
            *(uint32_t*)&ch[off] = pack_hi(v2, v3);
            *(uint32_t*)&cl[off] = pack_lo(v2, v3);
        }
    }
}

// ---------------- LayerNorm (+ optional split out) ----------------
__global__ __launch_bounds__(128)
void ln_kernel(float* __restrict__ out, const float* __restrict__ a,
               const float* __restrict__ y, const float* __restrict__ g,
               const float* __restrict__ bb,
               __nv_bfloat16* __restrict__ oh, __nv_bfloat16* __restrict__ ol)
{
    int row = blockIdx.x, tid = threadIdx.x;
    float4 v = ((const float4*)(a + (long)row * DM))[tid];
    if (y) {
        float4 vy = ((const float4*)(y + (long)row * DM))[tid];
        v.x += vy.x; v.y += vy.y; v.z += vy.z; v.w += vy.w;
    }
    float s  = v.x + v.y + v.z + v.w;
    float sq = v.x * v.x + v.y * v.y + v.z * v.z + v.w * v.w;
#pragma unroll
    for (int o = 16; o > 0; o >>= 1) {
        s  += __shfl_xor_sync(0xffffffffu, s,  o);
        sq += __shfl_xor_sync(0xffffffffu, sq, o);
    }
    __shared__ float shs[4], shq[4];
    int wid = tid >> 5;
    if ((tid & 31) == 0) { shs[wid] = s; shq[wid] = sq; }
    __syncthreads();
    s  = shs[0] + shs[1] + shs[2] + shs[3];
    sq = shq[0] + shq[1] + shq[2] + shq[3];
    float mean = s * (1.f / DM);
    float var  = sq * (1.f / DM) - mean * mean;
    float rstd = rsqrtf(var + 1e-5f);
    float4 gg = ((const float4*)g)[tid];
    float4 bv = ((const float4*)bb)[tid];
    float4 o4;
    o4.x = (v.x - mean) * rstd * gg.x + bv.x;
    o4.y = (v.y - mean) * rstd * gg.y + bv.y;
    o4.z = (v.z - mean) * rstd * gg.z + bv.z;
    o4.w = (v.w - mean) * rstd * gg.w + bv.w;
    ((float4*)(out + (long)row * DM))[tid] = o4;
    if (oh) {
        ((uint32_t*)(oh + (long)row * DM))[tid * 2]     = pack_hi(o4.x, o4.y);
        ((uint32_t*)(oh + (long)row * DM))[tid * 2 + 1] = pack_hi(o4.z, o4.w);
        ((uint32_t*)(ol + (long)row * DM))[tid * 2]     = pack_lo(o4.x, o4.y);
        ((uint32_t*)(ol + (long)row * DM))[tid * 2 + 1] = pack_lo(o4.z, o4.w);
    }
}

// ---------------- final FC on last token ----------------
__global__ __launch_bounds__(64)
void fc_kernel(const float* __restrict__ hin, const float* __restrict__ w,
               const float* __restrict__ b, float* __restrict__ out)
{
    __shared__ float sh[512];
    int tid = threadIdx.x;
    int bb  = blockIdx.x;
    const float* row = hin + ((long)bb * LSEQ + (LSEQ - 1)) * DM;
    for (int i = tid; i < 512; i += 64) sh[i] = row[i];
    __syncthreads();
    if (tid < 50) {
        float a = b[tid];
#pragma unroll 8
        for (int d = 0; d < 512; d++) a += sh[d] * w[d * 50 + tid];
        out[bb * 50 + tid] = a;
    }
}

// ---------------- launch ----------------
extern "C" void kernel_launch(void* const* d_in, const int* in_sizes, int n_in,
                              void* d_out, int out_size)
{
    const float* x     = (const float*)d_in[0];
    const float* emb_w = (const float*)d_in[1];
    const float* emb_b = (const float*)d_in[2];
    const float* pe    = (const float*)d_in[3];
    const float* Wq    = (const float*)d_in[4];
    const float* bq    = (const float*)d_in[5];
    const float* Wk    = (const float*)d_in[6];
    const float* bk    = (const float*)d_in[7];
    const float* Wv    = (const float*)d_in[8];
    const float* bv    = (const float*)d_in[9];
    const float* Wo    = (const float*)d_in[10];
    const float* bo    = (const float*)d_in[11];
    const float* W1    = (const float*)d_in[12];
    const float* b1    = (const float*)d_in[13];
    const float* W2    = (const float*)d_in[14];
    const float* b2    = (const float*)d_in[15];
    const float* g1    = (const float*)d_in[16];
    const float* be1   = (const float*)d_in[17];
    const float* g2    = (const float*)d_in[18];
    const float* be2   = (const float*)d_in[19];
    const float* lm_qw = (const float*)d_in[20];
    const float* lm_qb = (const float*)d_in[21];
    const float* lm_kw = (const float*)d_in[22];
    const float* lm_kb = (const float*)d_in[23];
    const float* gn    = (const float*)d_in[24];
    const float* bn    = (const float*)d_in[25];
    const float* fc_w  = (const float*)d_in[26];
    const float* fc_b  = (const float*)d_in[27];
    float* out = (float*)d_out;

    float *h, *t1, *t2;
    cudaGetSymbolAddress((void**)&h,  g_h);
    cudaGetSymbolAddress((void**)&t1, g_t1);
    cudaGetSymbolAddress((void**)&t2, g_t2);

    __nv_bfloat16 *wqh, *wql, *wkh, *wkl, *wvh, *wvl, *woh, *wol;
    __nv_bfloat16 *w1h, *w1l, *w2h, *w2l, *ah, *al, *ffh, *ffl;
    __nv_bfloat16 *qh, *ql, *kh, *kl, *vh, *vl, *qpb, *kpb;
    cudaGetSymbolAddress((void**)&wqh, g_wqh);
    cudaGetSymbolAddress((void**)&wql, g_wql);
    cudaGetSymbolAddress((void**)&wkh, g_wkh);
    cudaGetSymbolAddress((void**)&wkl, g_wkl);
    cudaGetSymbolAddress((void**)&wvh, g_wvh);
    cudaGetSymbolAddress((void**)&wvl, g_wvl);
    cudaGetSymbolAddress((void**)&woh, g_woh);
    cudaGetSymbolAddress((void**)&wol, g_wol);
    cudaGetSymbolAddress((void**)&w1h, g_w1h);
    cudaGetSymbolAddress((void**)&w1l, g_w1l);
    cudaGetSymbolAddress((void**)&w2h, g_w2h);
    cudaGetSymbolAddress((void**)&w2l, g_w2l);
    cudaGetSymbolAddress((void**)&ah,  g_ah);
    cudaGetSymbolAddress((void**)&al,  g_al);
    cudaGetSymbolAddress((void**)&ffh, g_ffh);
    cudaGetSymbolAddress((void**)&ffl, g_ffl);
    cudaGetSymbolAddress((void**)&qh,  g_qh);
    cudaGetSymbolAddress((void**)&ql,  g_ql);
    cudaGetSymbolAddress((void**)&kh,  g_kh);
    cudaGetSymbolAddress((void**)&kl,  g_kl);
    cudaGetSymbolAddress((void**)&vh,  g_vh);
    cudaGetSymbolAddress((void**)&vl,  g_vl);
    cudaGetSymbolAddress((void**)&qpb, g_qp);
    cudaGetSymbolAddress((void**)&kpb, g_kp);

    cudaFuncSetAttribute(attn_kernel, cudaFuncAttributeMaxDynamicSharedMemorySize, ATT_SMEM);
    cudaFuncSetAttribute(mma_gemm,    cudaFuncAttributeMaxDynamicSharedMemorySize, MMA_SMEM);

    wsplit_all<<<NL * 3072, 256>>>(Wq, Wk, Wv, Wo, W1, W2,
                                   wqh, wql, wkh, wkl, wvh, wvl, woh, wol,
                                   w1h, w1l, w2h, w2l);
    embed_kernel<<<BL, 128>>>(x, emb_w, emb_b, pe, h, ah, al);

    const int MT = MPAD / 128;
    dim3 gq(DM / 128, MT);
    dim3 gf1(DFF / 128, MT);

    for (int i = 0; i < NL; i++) {
        long o512 = (long)i * DM * DM;
        long offf = (long)i * DM * DFF;

        // launch idx (layer 0): 2=Q, 3=K, 4=lmq, 5=V (ncu -s5 -c1 -> V mma_gemm)
        mma_gemm<<<gq, 256, MMA_SMEM>>>(ah, al, wqh + o512, wql + o512, bq + i * DM,
                                        (float*)0, qh, ql, DM, DM, 4);
        mma_gemm<<<gq, 256, MMA_SMEM>>>(ah, al, wkh + o512, wkl + o512, bk + i * DM,
                                        (float*)0, kh, kl, DM, DM, 4);
        lmproj_kernel<<<BL, 128>>>(qh, lm_qw, lm_qb, qpb);
        mma_gemm<<<gq, 256, MMA_SMEM>>>(ah, al, wvh + o512, wvl + o512, bv + i * DM,
                                        (float*)0, vh, vl, DM, DM, 4);
        lmproj_kernel<<<BL, 128>>>(kh, lm_kw, lm_kb, kpb);

        attn_kernel<<<NB * NH * 16, 128, ATT_SMEM>>>(qh, ql, kh, kl, vh, vl, qpb, kpb, ah, al);

        mma_gemm<<<gq, 256, MMA_SMEM>>>(ah, al, woh + o512, wol + o512, bo + i * DM, t1,
                                        (__nv_bfloat16*)0, (__nv_bfloat16*)0, DM, DM, 2);
        ln_kernel<<<BL, 128>>>(h, h, t1, g1 + i * DM, be1 + i * DM, ah, al);

        mma_gemm<<<gf1, 256, MMA_SMEM>>>(ah, al, w1h + offf, w1l + offf, b1 + i * DFF,
                                         (float*)0, ffh, ffl, DFF, DM, 5);
        mma_gemm<<<gq, 256, MMA_SMEM>>>(ffh, ffl, w2h + offf, w2l + offf, b2 + i * DM, t2,
                                        (__nv_bfloat16*)0, (__nv_bfloat16*)0, DM, DFF, 2);

        ln_kernel<<<BL, 128>>>(t1, h, t2, g2 + i * DM, be2 + i * DM,
                               (__nv_bfloat16*)0, (__nv_bfloat16*)0);
        ln_kernel<<<BL, 128>>>(h, t1, t2, g2 + i * DM, be2 + i * DM, ah, al);
    }

    ln_kernel<<<BL, 128>>>(t1, h, (const float*)nullptr, gn, bn,
                           (__nv_bfloat16*)0, (__nv_bfloat16*)0);
    fc_kernel<<<NB, 64>>>(t1, fc_w, fc_b, out);
}